// round 1
// baseline (speedup 1.0000x reference)
#include <cuda_runtime.h>
#include <math.h>

#define T 16384          // B*S tokens
#define D 1024
#define E 8
#define NTOPK 2
#define ROWCAP (2*T + E*128)   // padded assignment rows

// ---------------- scratch (device globals; no allocation allowed) ----------
__device__ int   g_counts[E];
__device__ int   g_cursor[E];
__device__ int   g_off[E];
__device__ int   g_topk_e[2*T];
__device__ float g_topk_w[2*T];
__device__ int   g_perm[ROWCAP];     // slot -> token
__device__ float g_permw[ROWCAP];    // slot -> routing weight
__device__ int   g_slot[2*T];        // (token,k) -> slot
__device__ float g_Y[(size_t)ROWCAP * D];   // per-assignment expert output (weighted, biased)

// ---------------- init ------------------------------------------------------
__global__ void k_init() {
    int i = threadIdx.x;
    if (i < E) { g_counts[i] = 0; g_cursor[i] = 0; }
}

// ---------------- router: warp per token ------------------------------------
__global__ __launch_bounds__(256) void k_router(
    const float* __restrict__ X, const float* __restrict__ Wr,
    const float* __restrict__ br)
{
    __shared__ float sWr[E * D];
    int tid = threadIdx.x;
    for (int i = tid; i < E * D; i += 256) sWr[i] = Wr[i];
    __syncthreads();

    int warp = tid >> 5, lane = tid & 31;
    int t = blockIdx.x * 8 + warp;
    const float* x = X + (size_t)t * D;

    float acc[E];
#pragma unroll
    for (int e = 0; e < E; e++) acc[e] = 0.f;

    for (int i = 0; i < D / 32; i++) {
        float xv = x[i * 32 + lane];
#pragma unroll
        for (int e = 0; e < E; e++) acc[e] += xv * sWr[e * D + i * 32 + lane];
    }
#pragma unroll
    for (int e = 0; e < E; e++) {
#pragma unroll
        for (int o = 16; o > 0; o >>= 1)
            acc[e] += __shfl_xor_sync(0xffffffffu, acc[e], o);
    }

    if (lane == 0) {
        float p[E];
        float m = -1e30f;
#pragma unroll
        for (int e = 0; e < E; e++) { p[e] = acc[e] + br[e]; m = fmaxf(m, p[e]); }
        float s = 0.f;
#pragma unroll
        for (int e = 0; e < E; e++) { p[e] = expf(p[e] - m); s += p[e]; }
        float inv = 1.f / s;
#pragma unroll
        for (int e = 0; e < E; e++) p[e] *= inv;

        // top-2, ties keep lower index (matches jax.lax.top_k)
        int e0 = 0;
#pragma unroll
        for (int e = 1; e < E; e++) if (p[e] > p[e0]) e0 = e;
        int e1 = (e0 == 0) ? 1 : 0;
#pragma unroll
        for (int e = 0; e < E; e++) if (e != e0 && p[e] > p[e1]) e1 = e;

        g_topk_e[2 * t + 0] = e0;  g_topk_w[2 * t + 0] = p[e0];
        g_topk_e[2 * t + 1] = e1;  g_topk_w[2 * t + 1] = p[e1];
        atomicAdd(&g_counts[e0], 1);
        atomicAdd(&g_counts[e1], 1);
    }
}

// ---------------- scan: 128-aligned expert offsets ---------------------------
__global__ void k_scan() {
    if (threadIdx.x == 0) {
        int off = 0;
        for (int e = 0; e < E; e++) {
            g_off[e] = off;
            off += ((g_counts[e] + 127) / 128) * 128;
        }
    }
}

// ---------------- scatter: build per-expert permutation ----------------------
__global__ __launch_bounds__(256) void k_scatter() {
    int idx = blockIdx.x * 256 + threadIdx.x;   // (token,k) pair
    if (idx >= 2 * T) return;
    int e = g_topk_e[idx];
    float w = g_topk_w[idx];
    int pos = atomicAdd(&g_cursor[e], 1);
    int slot = g_off[e] + pos;
    g_perm[slot]  = idx >> 1;   // token
    g_permw[slot] = w;
    g_slot[idx]   = slot;
}

// ---------------- expert GEMM: Y[slot] = w * (X[tok] @ We[e]^T + be[e]) ------
// grid: (D/128, T/128, E), block 256. 128x128x16 tile, 8x8 per thread.
__global__ __launch_bounds__(256) void k_expert_gemm(
    const float* __restrict__ X, const float* __restrict__ We,
    const float* __restrict__ be)
{
    int e = blockIdx.z;
    int cnt = g_counts[e];
    int row0 = blockIdx.y * 128;
    if (row0 >= cnt) return;
    int n0 = blockIdx.x * 128;
    int off = g_off[e];

    __shared__ float As[16][128];
    __shared__ float Bs[16][128];
    __shared__ int   sTok[128];
    __shared__ float sW[128];

    int tid = threadIdx.x;
    if (tid < 128) {
        int rl = row0 + tid;
        bool v = rl < cnt;
        sTok[tid] = v ? g_perm[off + rl] : -1;
        sW[tid]   = v ? g_permw[off + rl] : 0.f;
    }
    __syncthreads();

    int la = tid >> 2;          // 0..63
    int lk = (tid & 3) * 4;     // k offset for float4
    int tx = tid & 15, ty = tid >> 4;
    const float* Bbase = We + (size_t)e * D * D;

    float acc[8][8];
#pragma unroll
    for (int i = 0; i < 8; i++)
#pragma unroll
        for (int j = 0; j < 8; j++) acc[i][j] = 0.f;

    for (int k0 = 0; k0 < D; k0 += 16) {
#pragma unroll
        for (int r = 0; r < 128; r += 64) {
            int m = la + r;
            int tk = sTok[m];
            float4 v = (tk >= 0)
                ? *(const float4*)(X + (size_t)tk * D + k0 + lk)
                : make_float4(0.f, 0.f, 0.f, 0.f);
            As[lk + 0][m] = v.x; As[lk + 1][m] = v.y;
            As[lk + 2][m] = v.z; As[lk + 3][m] = v.w;
        }
#pragma unroll
        for (int r = 0; r < 128; r += 64) {
            int h = n0 + la + r;
            float4 v = *(const float4*)(Bbase + (size_t)h * D + k0 + lk);
            Bs[lk + 0][la + r] = v.x; Bs[lk + 1][la + r] = v.y;
            Bs[lk + 2][la + r] = v.z; Bs[lk + 3][la + r] = v.w;
        }
        __syncthreads();

#pragma unroll
        for (int k = 0; k < 16; k++) {
            float4 a0 = ((const float4*)As[k])[ty * 2];
            float4 a1 = ((const float4*)As[k])[ty * 2 + 1];
            float4 b0 = ((const float4*)Bs[k])[tx * 2];
            float4 b1 = ((const float4*)Bs[k])[tx * 2 + 1];
            float a[8] = {a0.x, a0.y, a0.z, a0.w, a1.x, a1.y, a1.z, a1.w};
            float b[8] = {b0.x, b0.y, b0.z, b0.w, b1.x, b1.y, b1.z, b1.w};
#pragma unroll
            for (int i = 0; i < 8; i++)
#pragma unroll
                for (int j = 0; j < 8; j++) acc[i][j] += a[i] * b[j];
        }
        __syncthreads();
    }

#pragma unroll
    for (int i = 0; i < 8; i++) {
        int m = ty * 8 + i;
        if (sTok[m] >= 0) {
            float w = sW[m];
            size_t rowp = (size_t)(off + row0 + m) * D;
#pragma unroll
            for (int j = 0; j < 8; j++) {
                int h = n0 + tx * 8 + j;
                g_Y[rowp + h] = w * (acc[i][j] + be[e * D + h]);
            }
        }
    }
}

// ---------------- output GEMM: out = (Y[s0]+Y[s1]) @ Wo^T + bo ---------------
// grid: (D/128, T/128), block 256.
__global__ __launch_bounds__(256) void k_out_gemm(
    const float* __restrict__ Wo, const float* __restrict__ bo,
    float* __restrict__ out)
{
    int m0 = blockIdx.y * 128;
    int n0 = blockIdx.x * 128;

    __shared__ float As[16][128];
    __shared__ float Bs[16][128];
    __shared__ int sS0[128];
    __shared__ int sS1[128];

    int tid = threadIdx.x;
    if (tid < 128) {
        int t = m0 + tid;
        sS0[tid] = g_slot[2 * t + 0];
        sS1[tid] = g_slot[2 * t + 1];
    }
    __syncthreads();

    int la = tid >> 2;
    int lk = (tid & 3) * 4;
    int tx = tid & 15, ty = tid >> 4;

    float acc[8][8];
#pragma unroll
    for (int i = 0; i < 8; i++)
#pragma unroll
        for (int j = 0; j < 8; j++) acc[i][j] = 0.f;

    for (int k0 = 0; k0 < D; k0 += 16) {
#pragma unroll
        for (int r = 0; r < 128; r += 64) {
            int m = la + r;
            const float* y0 = g_Y + (size_t)sS0[m] * D + k0 + lk;
            const float* y1 = g_Y + (size_t)sS1[m] * D + k0 + lk;
            float4 v0 = *(const float4*)y0;
            float4 v1 = *(const float4*)y1;
            As[lk + 0][m] = v0.x + v1.x; As[lk + 1][m] = v0.y + v1.y;
            As[lk + 2][m] = v0.z + v1.z; As[lk + 3][m] = v0.w + v1.w;
        }
#pragma unroll
        for (int r = 0; r < 128; r += 64) {
            int h = n0 + la + r;
            float4 v = *(const float4*)(Wo + (size_t)h * D + k0 + lk);
            Bs[lk + 0][la + r] = v.x; Bs[lk + 1][la + r] = v.y;
            Bs[lk + 2][la + r] = v.z; Bs[lk + 3][la + r] = v.w;
        }
        __syncthreads();

#pragma unroll
        for (int k = 0; k < 16; k++) {
            float4 a0 = ((const float4*)As[k])[ty * 2];
            float4 a1 = ((const float4*)As[k])[ty * 2 + 1];
            float4 b0 = ((const float4*)Bs[k])[tx * 2];
            float4 b1 = ((const float4*)Bs[k])[tx * 2 + 1];
            float a[8] = {a0.x, a0.y, a0.z, a0.w, a1.x, a1.y, a1.z, a1.w};
            float b[8] = {b0.x, b0.y, b0.z, b0.w, b1.x, b1.y, b1.z, b1.w};
#pragma unroll
            for (int i = 0; i < 8; i++)
#pragma unroll
                for (int j = 0; j < 8; j++) acc[i][j] += a[i] * b[j];
        }
        __syncthreads();
    }

#pragma unroll
    for (int i = 0; i < 8; i++) {
        int t = m0 + ty * 8 + i;
#pragma unroll
        for (int j = 0; j < 8; j++) {
            int h = n0 + tx * 8 + j;
            out[(size_t)t * D + h] = acc[i][j] + bo[h];
        }
    }
}

// ---------------- launch -----------------------------------------------------
extern "C" void kernel_launch(void* const* d_in, const int* in_sizes, int n_in,
                              void* d_out, int out_size)
{
    const float* X  = (const float*)d_in[0];
    const float* We = (const float*)d_in[1];
    const float* be = (const float*)d_in[2];
    const float* Wr = (const float*)d_in[3];
    const float* br = (const float*)d_in[4];
    const float* Wo = (const float*)d_in[5];
    const float* bo = (const float*)d_in[6];
    float* out = (float*)d_out;

    k_init<<<1, 32>>>();
    k_router<<<T / 8, 256>>>(X, Wr, br);
    k_scan<<<1, 1>>>();
    k_scatter<<<(2 * T) / 256, 256>>>();
    k_expert_gemm<<<dim3(D / 128, T / 128, E), 256>>>(X, We, be);
    k_out_gemm<<<dim3(D / 128, T / 128), 256>>>(Wo, bo, out);
}

// round 2
// speedup vs baseline: 1.0013x; 1.0013x over previous
#include <cuda_runtime.h>
#include <math.h>

#define T 16384          // B*S tokens
#define D 1024
#define E 8
#define NTOPK 2
#define ROWCAP (2*T + E*128)   // padded assignment rows

// ---------------- scratch (device globals; no allocation allowed) ----------
__device__ int   g_counts[E];
__device__ int   g_cursor[E];
__device__ int   g_off[E];
__device__ int   g_topk_e[2*T];
__device__ float g_topk_w[2*T];
__device__ int   g_perm[ROWCAP];     // slot -> token
__device__ float g_permw[ROWCAP];    // slot -> routing weight
__device__ int   g_slot[2*T];        // (token,k) -> slot
__device__ float g_Y[(size_t)ROWCAP * D];   // per-assignment expert output (weighted, biased)

// ---------------- init ------------------------------------------------------
__global__ void k_init() {
    int i = threadIdx.x;
    if (i < E) { g_counts[i] = 0; g_cursor[i] = 0; }
}

// ---------------- router: warp per token ------------------------------------
__global__ __launch_bounds__(256) void k_router(
    const float* __restrict__ X, const float* __restrict__ Wr,
    const float* __restrict__ br)
{
    __shared__ float sWr[E * D];
    int tid = threadIdx.x;
    for (int i = tid; i < E * D; i += 256) sWr[i] = Wr[i];
    __syncthreads();

    int warp = tid >> 5, lane = tid & 31;
    int t = blockIdx.x * 8 + warp;
    const float* x = X + (size_t)t * D;

    float acc[E];
#pragma unroll
    for (int e = 0; e < E; e++) acc[e] = 0.f;

    for (int i = 0; i < D / 32; i++) {
        float xv = x[i * 32 + lane];
#pragma unroll
        for (int e = 0; e < E; e++) acc[e] += xv * sWr[e * D + i * 32 + lane];
    }
#pragma unroll
    for (int e = 0; e < E; e++) {
#pragma unroll
        for (int o = 16; o > 0; o >>= 1)
            acc[e] += __shfl_xor_sync(0xffffffffu, acc[e], o);
    }

    if (lane == 0) {
        float p[E];
        float m = -1e30f;
#pragma unroll
        for (int e = 0; e < E; e++) { p[e] = acc[e] + br[e]; m = fmaxf(m, p[e]); }
        float s = 0.f;
#pragma unroll
        for (int e = 0; e < E; e++) { p[e] = expf(p[e] - m); s += p[e]; }
        float inv = 1.f / s;
#pragma unroll
        for (int e = 0; e < E; e++) p[e] *= inv;

        // top-2, ties keep lower index (matches jax.lax.top_k)
        int e0 = 0;
#pragma unroll
        for (int e = 1; e < E; e++) if (p[e] > p[e0]) e0 = e;
        int e1 = (e0 == 0) ? 1 : 0;
#pragma unroll
        for (int e = 0; e < E; e++) if (e != e0 && p[e] > p[e1]) e1 = e;

        g_topk_e[2 * t + 0] = e0;  g_topk_w[2 * t + 0] = p[e0];
        g_topk_e[2 * t + 1] = e1;  g_topk_w[2 * t + 1] = p[e1];
        atomicAdd(&g_counts[e0], 1);
        atomicAdd(&g_counts[e1], 1);
    }
}

// ---------------- scan: 128-aligned expert offsets ---------------------------
__global__ void k_scan() {
    if (threadIdx.x == 0) {
        int off = 0;
        for (int e = 0; e < E; e++) {
            g_off[e] = off;
            off += ((g_counts[e] + 127) / 128) * 128;
        }
    }
}

// ---------------- scatter: build per-expert permutation ----------------------
__global__ __launch_bounds__(256) void k_scatter() {
    int idx = blockIdx.x * 256 + threadIdx.x;   // (token,k) pair
    if (idx >= 2 * T) return;
    int e = g_topk_e[idx];
    float w = g_topk_w[idx];
    int pos = atomicAdd(&g_cursor[e], 1);
    int slot = g_off[e] + pos;
    g_perm[slot]  = idx >> 1;   // token
    g_permw[slot] = w;
    g_slot[idx]   = slot;
}

// ---------------- expert GEMM: Y[slot] = w * (X[tok] @ We[e]^T + be[e]) ------
// grid: (D/128, T/128, E), block 256. 128x128x16 tile, 8x8 per thread.
__global__ __launch_bounds__(256) void k_expert_gemm(
    const float* __restrict__ X, const float* __restrict__ We,
    const float* __restrict__ be)
{
    int e = blockIdx.z;
    int cnt = g_counts[e];
    int row0 = blockIdx.y * 128;
    if (row0 >= cnt) return;
    int n0 = blockIdx.x * 128;
    int off = g_off[e];

    __shared__ float As[16][128];
    __shared__ float Bs[16][128];
    __shared__ int   sTok[128];
    __shared__ float sW[128];

    int tid = threadIdx.x;
    if (tid < 128) {
        int rl = row0 + tid;
        bool v = rl < cnt;
        sTok[tid] = v ? g_perm[off + rl] : -1;
        sW[tid]   = v ? g_permw[off + rl] : 0.f;
    }
    __syncthreads();

    int la = tid >> 2;          // 0..63
    int lk = (tid & 3) * 4;     // k offset for float4
    int tx = tid & 15, ty = tid >> 4;
    const float* Bbase = We + (size_t)e * D * D;

    float acc[8][8];
#pragma unroll
    for (int i = 0; i < 8; i++)
#pragma unroll
        for (int j = 0; j < 8; j++) acc[i][j] = 0.f;

    for (int k0 = 0; k0 < D; k0 += 16) {
#pragma unroll
        for (int r = 0; r < 128; r += 64) {
            int m = la + r;
            int tk = sTok[m];
            float4 v = (tk >= 0)
                ? *(const float4*)(X + (size_t)tk * D + k0 + lk)
                : make_float4(0.f, 0.f, 0.f, 0.f);
            As[lk + 0][m] = v.x; As[lk + 1][m] = v.y;
            As[lk + 2][m] = v.z; As[lk + 3][m] = v.w;
        }
#pragma unroll
        for (int r = 0; r < 128; r += 64) {
            int h = n0 + la + r;
            float4 v = *(const float4*)(Bbase + (size_t)h * D + k0 + lk);
            Bs[lk + 0][la + r] = v.x; Bs[lk + 1][la + r] = v.y;
            Bs[lk + 2][la + r] = v.z; Bs[lk + 3][la + r] = v.w;
        }
        __syncthreads();

#pragma unroll
        for (int k = 0; k < 16; k++) {
            float4 a0 = ((const float4*)As[k])[ty * 2];
            float4 a1 = ((const float4*)As[k])[ty * 2 + 1];
            float4 b0 = ((const float4*)Bs[k])[tx * 2];
            float4 b1 = ((const float4*)Bs[k])[tx * 2 + 1];
            float a[8] = {a0.x, a0.y, a0.z, a0.w, a1.x, a1.y, a1.z, a1.w};
            float b[8] = {b0.x, b0.y, b0.z, b0.w, b1.x, b1.y, b1.z, b1.w};
#pragma unroll
            for (int i = 0; i < 8; i++)
#pragma unroll
                for (int j = 0; j < 8; j++) acc[i][j] += a[i] * b[j];
        }
        __syncthreads();
    }

#pragma unroll
    for (int i = 0; i < 8; i++) {
        int m = ty * 8 + i;
        if (sTok[m] >= 0) {
            float w = sW[m];
            size_t rowp = (size_t)(off + row0 + m) * D;
#pragma unroll
            for (int j = 0; j < 8; j++) {
                int h = n0 + tx * 8 + j;
                g_Y[rowp + h] = w * (acc[i][j] + be[e * D + h]);
            }
        }
    }
}

// ---------------- output GEMM: out = (Y[s0]+Y[s1]) @ Wo^T + bo ---------------
// grid: (D/128, T/128), block 256.
__global__ __launch_bounds__(256) void k_out_gemm(
    const float* __restrict__ Wo, const float* __restrict__ bo,
    float* __restrict__ out)
{
    int m0 = blockIdx.y * 128;
    int n0 = blockIdx.x * 128;

    __shared__ float As[16][128];
    __shared__ float Bs[16][128];
    __shared__ int sS0[128];
    __shared__ int sS1[128];

    int tid = threadIdx.x;
    if (tid < 128) {
        int t = m0 + tid;
        sS0[tid] = g_slot[2 * t + 0];
        sS1[tid] = g_slot[2 * t + 1];
    }
    __syncthreads();

    int la = tid >> 2;
    int lk = (tid & 3) * 4;
    int tx = tid & 15, ty = tid >> 4;

    float acc[8][8];
#pragma unroll
    for (int i = 0; i < 8; i++)
#pragma unroll
        for (int j = 0; j < 8; j++) acc[i][j] = 0.f;

    for (int k0 = 0; k0 < D; k0 += 16) {
#pragma unroll
        for (int r = 0; r < 128; r += 64) {
            int m = la + r;
            const float* y0 = g_Y + (size_t)sS0[m] * D + k0 + lk;
            const float* y1 = g_Y + (size_t)sS1[m] * D + k0 + lk;
            float4 v0 = *(const float4*)y0;
            float4 v1 = *(const float4*)y1;
            As[lk + 0][m] = v0.x + v1.x; As[lk + 1][m] = v0.y + v1.y;
            As[lk + 2][m] = v0.z + v1.z; As[lk + 3][m] = v0.w + v1.w;
        }
#pragma unroll
        for (int r = 0; r < 128; r += 64) {
            int h = n0 + la + r;
            float4 v = *(const float4*)(Wo + (size_t)h * D + k0 + lk);
            Bs[lk + 0][la + r] = v.x; Bs[lk + 1][la + r] = v.y;
            Bs[lk + 2][la + r] = v.z; Bs[lk + 3][la + r] = v.w;
        }
        __syncthreads();

#pragma unroll
        for (int k = 0; k < 16; k++) {
            float4 a0 = ((const float4*)As[k])[ty * 2];
            float4 a1 = ((const float4*)As[k])[ty * 2 + 1];
            float4 b0 = ((const float4*)Bs[k])[tx * 2];
            float4 b1 = ((const float4*)Bs[k])[tx * 2 + 1];
            float a[8] = {a0.x, a0.y, a0.z, a0.w, a1.x, a1.y, a1.z, a1.w};
            float b[8] = {b0.x, b0.y, b0.z, b0.w, b1.x, b1.y, b1.z, b1.w};
#pragma unroll
            for (int i = 0; i < 8; i++)
#pragma unroll
                for (int j = 0; j < 8; j++) acc[i][j] += a[i] * b[j];
        }
        __syncthreads();
    }

#pragma unroll
    for (int i = 0; i < 8; i++) {
        int t = m0 + ty * 8 + i;
#pragma unroll
        for (int j = 0; j < 8; j++) {
            int h = n0 + tx * 8 + j;
            out[(size_t)t * D + h] = acc[i][j] + bo[h];
        }
    }
}

// ---------------- launch -----------------------------------------------------
extern "C" void kernel_launch(void* const* d_in, const int* in_sizes, int n_in,
                              void* d_out, int out_size)
{
    const float* X  = (const float*)d_in[0];
    const float* We = (const float*)d_in[1];
    const float* be = (const float*)d_in[2];
    const float* Wr = (const float*)d_in[3];
    const float* br = (const float*)d_in[4];
    const float* Wo = (const float*)d_in[5];
    const float* bo = (const float*)d_in[6];
    float* out = (float*)d_out;

    k_init<<<1, 32>>>();
    k_router<<<T / 8, 256>>>(X, Wr, br);
    k_scan<<<1, 1>>>();
    k_scatter<<<(2 * T) / 256, 256>>>();
    k_expert_gemm<<<dim3(D / 128, T / 128, E), 256>>>(X, We, be);
    k_out_gemm<<<dim3(D / 128, T / 128), 256>>>(Wo, bo, out);
}

// round 4
// speedup vs baseline: 1.8900x; 1.8876x over previous
#include <cuda_runtime.h>
#include <cuda_bf16.h>
#include <math.h>
#include <stdint.h>

#define T 16384          // B*S tokens
#define D 1024
#define E 8
#define ROWCAP (2*T + E*128)
#define KCH 32           // k per chunk
#define NC (D/KCH)       // 32 chunks
// per-buffer layout (bytes): Ahi[2][4096] Alo[2][4096] Bhi[2][4096] Blo[2][4096]
#define AHI 0
#define ALO 8192
#define BHI 16384
#define BLO 24576
#define BUF_B 32768
#define SMEM_DYN (1024 + 2*BUF_B)

// ---------------- scratch ----------------------------------------------------
__device__ int   g_counts[E];
__device__ int   g_cursor[E];
__device__ int   g_off[E];
__device__ int   g_topk_e[2*T];
__device__ float g_topk_w[2*T];
__device__ int   g_perm[ROWCAP];
__device__ float g_permw[ROWCAP];
__device__ int   g_slot[2*T];
__device__ float g_Y[(size_t)ROWCAP * D];

// ---------------- helpers ----------------------------------------------------
__device__ __forceinline__ uint32_t smem_u32(const void* p) {
    uint32_t a;
    asm("{ .reg .u64 t; cvta.to.shared.u64 t, %1; cvt.u32.u64 %0, t; }" : "=r"(a) : "l"(p));
    return a;
}

__device__ __forceinline__ void ldsm4(uint32_t* r, uint32_t a) {
    asm volatile("ldmatrix.sync.aligned.m8n8.x4.shared.b16 {%0,%1,%2,%3}, [%4];"
        : "=r"(r[0]), "=r"(r[1]), "=r"(r[2]), "=r"(r[3]) : "r"(a));
}

__device__ __forceinline__ void mma_bf16(float* d, const uint32_t* a, const uint32_t* b) {
    asm volatile("mma.sync.aligned.m16n8k16.row.col.f32.bf16.bf16.f32 "
        "{%0,%1,%2,%3},{%4,%5,%6,%7},{%8,%9},{%0,%1,%2,%3};"
        : "+f"(d[0]), "+f"(d[1]), "+f"(d[2]), "+f"(d[3])
        : "r"(a[0]), "r"(a[1]), "r"(a[2]), "r"(a[3]), "r"(b[0]), "r"(b[1]));
}

// swizzled byte offset within a 4KB (128 rows x 32B) k16 sub-tile
__device__ __forceinline__ int swz(int r, int h) {
    return (((r << 1) | h) ^ ((r >> 2) & 1)) << 4;
}

// split fp32x4 -> bf16 hi/lo, store 8B each
__device__ __forceinline__ void split_sts(char* hp, char* lp, float4 v) {
    float a[4] = {v.x, v.y, v.z, v.w};
    unsigned short h[4], l[4];
#pragma unroll
    for (int i = 0; i < 4; i++) {
        __nv_bfloat16 hb = __float2bfloat16(a[i]);
        h[i] = __bfloat16_as_ushort(hb);
        l[i] = __bfloat16_as_ushort(__float2bfloat16(a[i] - __bfloat162float(hb)));
    }
    *(uint2*)hp = make_uint2((uint32_t)h[0] | ((uint32_t)h[1] << 16),
                             (uint32_t)h[2] | ((uint32_t)h[3] << 16));
    *(uint2*)lp = make_uint2((uint32_t)l[0] | ((uint32_t)l[1] << 16),
                             (uint32_t)l[2] | ((uint32_t)l[3] << 16));
}

// ---------------- init / router / scan / scatter -----------------------------
__global__ void k_init() {
    int i = threadIdx.x;
    if (i < E) { g_counts[i] = 0; g_cursor[i] = 0; }
}

__global__ __launch_bounds__(256) void k_router(
    const float* __restrict__ X, const float* __restrict__ Wr,
    const float* __restrict__ br)
{
    __shared__ float sWr[E * D];
    int tid = threadIdx.x;
    for (int i = tid; i < E * D; i += 256) sWr[i] = Wr[i];
    __syncthreads();

    int warp = tid >> 5, lane = tid & 31;
    int t = blockIdx.x * 8 + warp;
    const float* x = X + (size_t)t * D;

    float acc[E];
#pragma unroll
    for (int e = 0; e < E; e++) acc[e] = 0.f;
    for (int i = 0; i < D / 32; i++) {
        float xv = x[i * 32 + lane];
#pragma unroll
        for (int e = 0; e < E; e++) acc[e] += xv * sWr[e * D + i * 32 + lane];
    }
#pragma unroll
    for (int e = 0; e < E; e++) {
#pragma unroll
        for (int o = 16; o > 0; o >>= 1)
            acc[e] += __shfl_xor_sync(0xffffffffu, acc[e], o);
    }
    if (lane == 0) {
        float p[E], m = -1e30f;
#pragma unroll
        for (int e = 0; e < E; e++) { p[e] = acc[e] + br[e]; m = fmaxf(m, p[e]); }
        float s = 0.f;
#pragma unroll
        for (int e = 0; e < E; e++) { p[e] = expf(p[e] - m); s += p[e]; }
        float inv = 1.f / s;
#pragma unroll
        for (int e = 0; e < E; e++) p[e] *= inv;
        int e0 = 0;
#pragma unroll
        for (int e = 1; e < E; e++) if (p[e] > p[e0]) e0 = e;
        int e1 = (e0 == 0) ? 1 : 0;
#pragma unroll
        for (int e = 0; e < E; e++) if (e != e0 && p[e] > p[e1]) e1 = e;
        g_topk_e[2 * t + 0] = e0;  g_topk_w[2 * t + 0] = p[e0];
        g_topk_e[2 * t + 1] = e1;  g_topk_w[2 * t + 1] = p[e1];
        atomicAdd(&g_counts[e0], 1);
        atomicAdd(&g_counts[e1], 1);
    }
}

__global__ void k_scan() {
    if (threadIdx.x == 0) {
        int off = 0;
        for (int e = 0; e < E; e++) {
            g_off[e] = off;
            off += ((g_counts[e] + 127) / 128) * 128;
        }
    }
}

__global__ __launch_bounds__(256) void k_scatter() {
    int idx = blockIdx.x * 256 + threadIdx.x;
    if (idx >= 2 * T) return;
    int e = g_topk_e[idx];
    float w = g_topk_w[idx];
    int pos = atomicAdd(&g_cursor[e], 1);
    int slot = g_off[e] + pos;
    g_perm[slot]  = idx >> 1;
    g_permw[slot] = w;
    g_slot[idx]   = slot;
}

// ===== shared compute: 2 k16 steps on one buffer ==============================
// acc[4][4][4], lane-offsets precomputed per thread.
#define COMPUTE_BUFFER(bufbase)                                               \
    do {                                                                      \
        _Pragma("unroll")                                                     \
        for (int ks = 0; ks < 2; ks++) {                                      \
            uint32_t ahB = (bufbase) + AHI + ks * 4096;                       \
            uint32_t alB = (bufbase) + ALO + ks * 4096;                       \
            uint32_t bhB = (bufbase) + BHI + ks * 4096;                       \
            uint32_t blB = (bufbase) + BLO + ks * 4096;                       \
            uint32_t ahi[4][4], alo[4][4], bhi[2][4], blo[2][4];              \
            _Pragma("unroll")                                                 \
            for (int mf = 0; mf < 4; mf++) {                                  \
                ldsm4(ahi[mf], ahB + aoff[mf]);                               \
                ldsm4(alo[mf], alB + aoff[mf]);                               \
            }                                                                 \
            _Pragma("unroll")                                                 \
            for (int p = 0; p < 2; p++) {                                     \
                ldsm4(bhi[p], bhB + boff[p]);                                 \
                ldsm4(blo[p], blB + boff[p]);                                 \
            }                                                                 \
            _Pragma("unroll")                                                 \
            for (int mf = 0; mf < 4; mf++)                                    \
                _Pragma("unroll")                                             \
                for (int nf = 0; nf < 4; nf++) {                              \
                    uint32_t* bh = &bhi[nf >> 1][(nf & 1) * 2];               \
                    uint32_t* bl = &blo[nf >> 1][(nf & 1) * 2];               \
                    mma_bf16(acc[mf][nf], ahi[mf], bh);                       \
                    mma_bf16(acc[mf][nf], ahi[mf], bl);                       \
                    mma_bf16(acc[mf][nf], alo[mf], bh);                       \
                }                                                             \
        }                                                                     \
    } while (0)

#define STS_CHUNK(bufptr)                                                     \
    do {                                                                      \
        _Pragma("unroll")                                                     \
        for (int i = 0; i < 4; i++) {                                         \
            int idx = i * 256 + tid;                                          \
            int r = idx >> 3, k4 = idx & 7;                                   \
            int off = (k4 >> 2) * 4096 + swz(r, (k4 >> 1) & 1) + (k4 & 1) * 8;\
            split_sts((bufptr) + AHI + off, (bufptr) + ALO + off, va[i]);     \
            split_sts((bufptr) + BHI + off, (bufptr) + BLO + off, vb[i]);     \
        }                                                                     \
    } while (0)

// ---------------- expert GEMM: Y[slot] = w * (X[tok] @ We[e]^T + be[e]) ------
__global__ __launch_bounds__(256, 1) void k_expert_gemm(
    const float* __restrict__ X, const float* __restrict__ We,
    const float* __restrict__ be)
{
    int e = blockIdx.z;
    int cnt = g_counts[e];
    int row0 = blockIdx.y * 128;
    if (row0 >= cnt) return;
    int n0 = blockIdx.x * 128;
    int off = g_off[e];

    extern __shared__ char smem[];
    int* sTok = (int*)smem;
    float* sW = (float*)(smem + 512);
    char* bufs = smem + 1024;
    uint32_t bufs_u = smem_u32(bufs);

    int tid = threadIdx.x, lane = tid & 31, warp = tid >> 5;
    int wm = warp >> 2, wn = warp & 3;
    const float* Bb = We + (size_t)e * D * D;

    if (tid < 128) {
        int rl = row0 + tid;
        bool v = rl < cnt;
        sTok[tid] = v ? g_perm[off + rl] : -1;
        sW[tid]   = v ? g_permw[off + rl] : 0.f;
    }
    __syncthreads();

    // ldmatrix lane offsets
    int aoff[4], boff[2];
    {
        int ar = lane & 15, ah = lane >> 4;
#pragma unroll
        for (int mf = 0; mf < 4; mf++) aoff[mf] = swz(wm * 64 + mf * 16 + ar, ah);
        int bj = lane >> 3;
        int bn = (lane & 7) + ((bj >> 1) << 3);
        int bh = bj & 1;
#pragma unroll
        for (int p = 0; p < 2; p++) boff[p] = swz(wn * 32 + p * 16 + bn, bh);
    }

    float acc[4][4][4];
#pragma unroll
    for (int mf = 0; mf < 4; mf++)
#pragma unroll
        for (int nf = 0; nf < 4; nf++)
#pragma unroll
            for (int q = 0; q < 4; q++) acc[mf][nf][q] = 0.f;

    float4 va[4], vb[4];
    int ldg_r[4], ldg_k4[4];
#pragma unroll
    for (int i = 0; i < 4; i++) {
        int idx = i * 256 + tid;
        ldg_r[i] = idx >> 3; ldg_k4[i] = idx & 7;
    }

    auto ldg_chunk = [&](int k0) {
#pragma unroll
        for (int i = 0; i < 4; i++) {
            int tk = sTok[ldg_r[i]];
            va[i] = (tk >= 0)
                ? *(const float4*)(X + (size_t)tk * D + k0 + ldg_k4[i] * 4)
                : make_float4(0.f, 0.f, 0.f, 0.f);
            vb[i] = *(const float4*)(Bb + (size_t)(n0 + ldg_r[i]) * D + k0 + ldg_k4[i] * 4);
        }
    };

    ldg_chunk(0);
    STS_CHUNK(bufs);
    __syncthreads();

    for (int c = 0; c < NC; c++) {
        if (c + 1 < NC) ldg_chunk((c + 1) * KCH);
        uint32_t cur = bufs_u + (c & 1) * BUF_B;
        COMPUTE_BUFFER(cur);
        if (c + 1 < NC) {
            __syncthreads();
            STS_CHUNK(bufs + ((c + 1) & 1) * BUF_B);
            __syncthreads();
        }
    }

    // epilogue
#pragma unroll
    for (int mf = 0; mf < 4; mf++) {
        int m0l = wm * 64 + mf * 16 + (lane >> 2);
#pragma unroll
        for (int nf = 0; nf < 4; nf++) {
            int n = wn * 32 + nf * 8 + (lane & 3) * 2;
            const float* bep = be + e * D + n0 + n;
            float b0 = bep[0], b1 = bep[1];
#pragma unroll
            for (int half = 0; half < 2; half++) {
                int m = m0l + half * 8;
                if (sTok[m] >= 0) {
                    float w = sW[m];
                    float2 o;
                    o.x = w * (acc[mf][nf][half * 2 + 0] + b0);
                    o.y = w * (acc[mf][nf][half * 2 + 1] + b1);
                    *(float2*)(g_Y + (size_t)(off + row0 + m) * D + n0 + n) = o;
                }
            }
        }
    }
}

// ---------------- output GEMM: out = (Y[s0]+Y[s1]) @ Wo^T + bo ---------------
__global__ __launch_bounds__(256, 1) void k_out_gemm(
    const float* __restrict__ Wo, const float* __restrict__ bo,
    float* __restrict__ out)
{
    int m0 = blockIdx.y * 128;
    int n0 = blockIdx.x * 128;

    extern __shared__ char smem[];
    int* sS0 = (int*)smem;
    int* sS1 = (int*)(smem + 512);
    char* bufs = smem + 1024;
    uint32_t bufs_u = smem_u32(bufs);

    int tid = threadIdx.x, lane = tid & 31, warp = tid >> 5;
    int wm = warp >> 2, wn = warp & 3;

    if (tid < 128) {
        int t = m0 + tid;
        sS0[tid] = g_slot[2 * t + 0];
        sS1[tid] = g_slot[2 * t + 1];
    }
    __syncthreads();

    int aoff[4], boff[2];
    {
        int ar = lane & 15, ah = lane >> 4;
#pragma unroll
        for (int mf = 0; mf < 4; mf++) aoff[mf] = swz(wm * 64 + mf * 16 + ar, ah);
        int bj = lane >> 3;
        int bn = (lane & 7) + ((bj >> 1) << 3);
        int bh = bj & 1;
#pragma unroll
        for (int p = 0; p < 2; p++) boff[p] = swz(wn * 32 + p * 16 + bn, bh);
    }

    float acc[4][4][4];
#pragma unroll
    for (int mf = 0; mf < 4; mf++)
#pragma unroll
        for (int nf = 0; nf < 4; nf++)
#pragma unroll
            for (int q = 0; q < 4; q++) acc[mf][nf][q] = 0.f;

    float4 va[4], vb[4];
    int ldg_r[4], ldg_k4[4];
#pragma unroll
    for (int i = 0; i < 4; i++) {
        int idx = i * 256 + tid;
        ldg_r[i] = idx >> 3; ldg_k4[i] = idx & 7;
    }

    auto ldg_chunk = [&](int k0) {
#pragma unroll
        for (int i = 0; i < 4; i++) {
            const float* p0 = g_Y + (size_t)sS0[ldg_r[i]] * D + k0 + ldg_k4[i] * 4;
            const float* p1 = g_Y + (size_t)sS1[ldg_r[i]] * D + k0 + ldg_k4[i] * 4;
            float4 v0 = *(const float4*)p0;
            float4 v1 = *(const float4*)p1;
            va[i] = make_float4(v0.x + v1.x, v0.y + v1.y, v0.z + v1.z, v0.w + v1.w);
            vb[i] = *(const float4*)(Wo + (size_t)(n0 + ldg_r[i]) * D + k0 + ldg_k4[i] * 4);
        }
    };

    ldg_chunk(0);
    STS_CHUNK(bufs);
    __syncthreads();

    for (int c = 0; c < NC; c++) {
        if (c + 1 < NC) ldg_chunk((c + 1) * KCH);
        uint32_t cur = bufs_u + (c & 1) * BUF_B;
        COMPUTE_BUFFER(cur);
        if (c + 1 < NC) {
            __syncthreads();
            STS_CHUNK(bufs + ((c + 1) & 1) * BUF_B);
            __syncthreads();
        }
    }

#pragma unroll
    for (int mf = 0; mf < 4; mf++) {
        int m0l = wm * 64 + mf * 16 + (lane >> 2);
#pragma unroll
        for (int nf = 0; nf < 4; nf++) {
            int n = wn * 32 + nf * 8 + (lane & 3) * 2;
            const float* bop = bo + n0 + n;
            float b0 = bop[0], b1 = bop[1];
#pragma unroll
            for (int half = 0; half < 2; half++) {
                int m = m0l + half * 8;
                float2 o;
                o.x = acc[mf][nf][half * 2 + 0] + b0;
                o.y = acc[mf][nf][half * 2 + 1] + b1;
                *(float2*)(out + (size_t)(m0 + m) * D + n0 + n) = o;
            }
        }
    }
}

// ---------------- launch -----------------------------------------------------
extern "C" void kernel_launch(void* const* d_in, const int* in_sizes, int n_in,
                              void* d_out, int out_size)
{
    const float* X  = (const float*)d_in[0];
    const float* We = (const float*)d_in[1];
    const float* be = (const float*)d_in[2];
    const float* Wr = (const float*)d_in[3];
    const float* br = (const float*)d_in[4];
    const float* Wo = (const float*)d_in[5];
    const float* bo = (const float*)d_in[6];
    float* out = (float*)d_out;

    static int smem_set = 0;
    if (!smem_set) {
        cudaFuncSetAttribute(k_expert_gemm, cudaFuncAttributeMaxDynamicSharedMemorySize, SMEM_DYN);
        cudaFuncSetAttribute(k_out_gemm,    cudaFuncAttributeMaxDynamicSharedMemorySize, SMEM_DYN);
        smem_set = 1;
    }

    k_init<<<1, 32>>>();
    k_router<<<T / 8, 256>>>(X, Wr, br);
    k_scan<<<1, 1>>>();
    k_scatter<<<(2 * T) / 256, 256>>>();
    k_expert_gemm<<<dim3(D / 128, T / 128, E), 256, SMEM_DYN>>>(X, We, be);
    k_out_gemm<<<dim3(D / 128, T / 128), 256, SMEM_DYN>>>(Wo, bo, out);
}

// round 5
// speedup vs baseline: 2.4117x; 1.2760x over previous
#include <cuda_runtime.h>
#include <cuda_bf16.h>
#include <math.h>
#include <stdint.h>

#define T 16384          // B*S tokens
#define D 1024
#define E 8
#define ROWCAP (2*T + E*128)
#define KCH 32           // k per pipeline stage
#define NC (D/KCH)       // 32 chunks
#define NSTAGE 4
// per-stage layout (bytes): Ahi[2][4096] Alo[2][4096] Bhi[2][4096] Blo[2][4096]
#define AHI 0
#define ALO 8192
#define BHI 16384
#define BLO 24576
#define STAGE_B 32768
#define SMEM_DYN (1024 + NSTAGE*STAGE_B)

// ---------------- scratch ----------------------------------------------------
__device__ int   g_counts[E];
__device__ int   g_cursor[E];
__device__ int   g_off[E];
__device__ int   g_topk_e[2*T];
__device__ float g_topk_w[2*T];
__device__ int   g_perm[ROWCAP];
__device__ float g_permw[ROWCAP];
__device__ int   g_slot[2*T];
__device__ float g_Y[(size_t)ROWCAP * D];
// preconverted bf16 hi/lo operands
__device__ __nv_bfloat16 g_Xhi[(size_t)T*D],  g_Xlo[(size_t)T*D];
__device__ __nv_bfloat16 g_Wehi[(size_t)E*D*D], g_Welo[(size_t)E*D*D];
__device__ __nv_bfloat16 g_Wohi[(size_t)D*D], g_Wolo[(size_t)D*D];
__device__ __nv_bfloat16 g_Chi[(size_t)T*D],  g_Clo[(size_t)T*D];

// ---------------- helpers ----------------------------------------------------
__device__ __forceinline__ uint32_t smem_u32(const void* p) {
    uint32_t a;
    asm("{ .reg .u64 t; cvta.to.shared.u64 t, %1; cvt.u32.u64 %0, t; }" : "=r"(a) : "l"(p));
    return a;
}

__device__ __forceinline__ void ldsm4(uint32_t* r, uint32_t a) {
    asm volatile("ldmatrix.sync.aligned.m8n8.x4.shared.b16 {%0,%1,%2,%3}, [%4];"
        : "=r"(r[0]), "=r"(r[1]), "=r"(r[2]), "=r"(r[3]) : "r"(a));
}

__device__ __forceinline__ void mma_bf16(float* d, const uint32_t* a, const uint32_t* b) {
    asm volatile("mma.sync.aligned.m16n8k16.row.col.f32.bf16.bf16.f32 "
        "{%0,%1,%2,%3},{%4,%5,%6,%7},{%8,%9},{%0,%1,%2,%3};"
        : "+f"(d[0]), "+f"(d[1]), "+f"(d[2]), "+f"(d[3])
        : "r"(a[0]), "r"(a[1]), "r"(a[2]), "r"(a[3]), "r"(b[0]), "r"(b[1]));
}

__device__ __forceinline__ void cp16(uint32_t dst, const void* src) {
    asm volatile("cp.async.cg.shared.global [%0], [%1], 16;" :: "r"(dst), "l"(src));
}
#define CP_COMMIT() asm volatile("cp.async.commit_group;" ::: "memory")
#define CP_WAIT2()  asm volatile("cp.async.wait_group 2;" ::: "memory")

// swizzled byte offset within a 4KB (128 rows x 32B) k16 sub-tile
__device__ __forceinline__ int swz(int r, int h) {
    return (((r << 1) | h) ^ ((r >> 2) & 1)) << 4;
}

// split fp32x4 -> two packed bf16x4 (uint2)
__device__ __forceinline__ void split4(float4 v, uint2* ho, uint2* lo) {
    float a[4] = {v.x, v.y, v.z, v.w};
    unsigned short h[4], l[4];
#pragma unroll
    for (int i = 0; i < 4; i++) {
        __nv_bfloat16 hb = __float2bfloat16(a[i]);
        h[i] = __bfloat16_as_ushort(hb);
        l[i] = __bfloat16_as_ushort(__float2bfloat16(a[i] - __bfloat162float(hb)));
    }
    *ho = make_uint2((uint32_t)h[0] | ((uint32_t)h[1] << 16),
                     (uint32_t)h[2] | ((uint32_t)h[3] << 16));
    *lo = make_uint2((uint32_t)l[0] | ((uint32_t)l[1] << 16),
                     (uint32_t)l[2] | ((uint32_t)l[3] << 16));
}

// ---------------- convert: fp32 -> bf16 hi/lo --------------------------------
__global__ __launch_bounds__(256) void k_convert(
    const float4* __restrict__ in, uint2* __restrict__ hi,
    uint2* __restrict__ lo, int n4)
{
    for (int i = blockIdx.x * 256 + threadIdx.x; i < n4; i += gridDim.x * 256) {
        uint2 h, l;
        split4(in[i], &h, &l);
        hi[i] = h; lo[i] = l;
    }
}

// ---------------- init / router / scan / scatter -----------------------------
__global__ void k_init() {
    int i = threadIdx.x;
    if (i < E) { g_counts[i] = 0; g_cursor[i] = 0; }
}

__global__ __launch_bounds__(256) void k_router(
    const float* __restrict__ X, const float* __restrict__ Wr,
    const float* __restrict__ br)
{
    __shared__ float sWr[E * D];
    int tid = threadIdx.x;
    for (int i = tid; i < E * D; i += 256) sWr[i] = Wr[i];
    __syncthreads();

    int warp = tid >> 5, lane = tid & 31;
    int t = blockIdx.x * 8 + warp;
    const float* x = X + (size_t)t * D;

    float acc[E];
#pragma unroll
    for (int e = 0; e < E; e++) acc[e] = 0.f;
    for (int i = 0; i < D / 32; i++) {
        float xv = x[i * 32 + lane];
#pragma unroll
        for (int e = 0; e < E; e++) acc[e] += xv * sWr[e * D + i * 32 + lane];
    }
#pragma unroll
    for (int e = 0; e < E; e++) {
#pragma unroll
        for (int o = 16; o > 0; o >>= 1)
            acc[e] += __shfl_xor_sync(0xffffffffu, acc[e], o);
    }
    if (lane == 0) {
        float p[E], m = -1e30f;
#pragma unroll
        for (int e = 0; e < E; e++) { p[e] = acc[e] + br[e]; m = fmaxf(m, p[e]); }
        float s = 0.f;
#pragma unroll
        for (int e = 0; e < E; e++) { p[e] = expf(p[e] - m); s += p[e]; }
        float inv = 1.f / s;
#pragma unroll
        for (int e = 0; e < E; e++) p[e] *= inv;
        int e0 = 0;
#pragma unroll
        for (int e = 1; e < E; e++) if (p[e] > p[e0]) e0 = e;
        int e1 = (e0 == 0) ? 1 : 0;
#pragma unroll
        for (int e = 0; e < E; e++) if (e != e0 && p[e] > p[e1]) e1 = e;
        g_topk_e[2 * t + 0] = e0;  g_topk_w[2 * t + 0] = p[e0];
        g_topk_e[2 * t + 1] = e1;  g_topk_w[2 * t + 1] = p[e1];
        atomicAdd(&g_counts[e0], 1);
        atomicAdd(&g_counts[e1], 1);
    }
}

__global__ void k_scan() {
    if (threadIdx.x == 0) {
        int off = 0;
        for (int e = 0; e < E; e++) {
            g_off[e] = off;
            off += ((g_counts[e] + 127) / 128) * 128;
        }
    }
}

__global__ __launch_bounds__(256) void k_scatter() {
    int idx = blockIdx.x * 256 + threadIdx.x;
    if (idx >= 2 * T) return;
    int e = g_topk_e[idx];
    float w = g_topk_w[idx];
    int pos = atomicAdd(&g_cursor[e], 1);
    int slot = g_off[e] + pos;
    g_perm[slot]  = idx >> 1;
    g_permw[slot] = w;
    g_slot[idx]   = slot;
}

// ---------------- combine: C[t] = Y[s0]+Y[s1] -> bf16 hi/lo ------------------
__global__ __launch_bounds__(256) void k_combine() {
    int idx = blockIdx.x * 256 + threadIdx.x;        // over T*D/4
    int t = idx >> 8;                                 // D/4 = 256 float4/row
    int c4 = idx & 255;
    int s0 = g_slot[2 * t + 0], s1 = g_slot[2 * t + 1];
    float4 a = ((const float4*)g_Y)[(size_t)s0 * 256 + c4];
    float4 b = ((const float4*)g_Y)[(size_t)s1 * 256 + c4];
    float4 v = make_float4(a.x + b.x, a.y + b.y, a.z + b.z, a.w + b.w);
    uint2 h, l;
    split4(v, &h, &l);
    ((uint2*)g_Chi)[idx] = h;
    ((uint2*)g_Clo)[idx] = l;
}

// ===== shared compute: 2 k16 steps on one stage ===============================
#define COMPUTE_STAGE(bufbase)                                                \
    do {                                                                      \
        _Pragma("unroll")                                                     \
        for (int ks = 0; ks < 2; ks++) {                                      \
            uint32_t ahB = (bufbase) + AHI + ks * 4096;                       \
            uint32_t alB = (bufbase) + ALO + ks * 4096;                       \
            uint32_t bhB = (bufbase) + BHI + ks * 4096;                       \
            uint32_t blB = (bufbase) + BLO + ks * 4096;                       \
            uint32_t ahi[4][4], alo[4][4], bhi[2][4], blo[2][4];              \
            _Pragma("unroll")                                                 \
            for (int mf = 0; mf < 4; mf++) {                                  \
                ldsm4(ahi[mf], ahB + aoff[mf]);                               \
                ldsm4(alo[mf], alB + aoff[mf]);                               \
            }                                                                 \
            _Pragma("unroll")                                                 \
            for (int p = 0; p < 2; p++) {                                     \
                ldsm4(bhi[p], bhB + boff[p]);                                 \
                ldsm4(blo[p], blB + boff[p]);                                 \
            }                                                                 \
            _Pragma("unroll")                                                 \
            for (int mf = 0; mf < 4; mf++)                                    \
                _Pragma("unroll")                                             \
                for (int nf = 0; nf < 4; nf++) {                              \
                    uint32_t* bh = &bhi[nf >> 1][(nf & 1) * 2];               \
                    uint32_t* bl = &blo[nf >> 1][(nf & 1) * 2];               \
                    mma_bf16(acc[mf][nf], ahi[mf], bh);                       \
                    mma_bf16(acc[mf][nf], ahi[mf], bl);                       \
                    mma_bf16(acc[mf][nf], alo[mf], bh);                       \
                }                                                             \
        }                                                                     \
    } while (0)

#define SETUP_LDSM_OFFS()                                                     \
    int aoff[4], boff[2];                                                     \
    {                                                                         \
        int ar = lane & 15, ah = lane >> 4;                                   \
        _Pragma("unroll")                                                     \
        for (int mf = 0; mf < 4; mf++) aoff[mf] = swz(wm * 64 + mf * 16 + ar, ah); \
        int bj = lane >> 3;                                                   \
        int bn = (lane & 7) + ((bj >> 1) << 3);                               \
        int bh_ = bj & 1;                                                     \
        _Pragma("unroll")                                                     \
        for (int p = 0; p < 2; p++) boff[p] = swz(wn * 32 + p * 16 + bn, bh_);\
    }

// per-thread: 8 segments/stage. seg = i*256+tid; part=seg>>9; r=(seg>>2)&127; s=seg&3
#define SETUP_SEGS(APTR_HI, APTR_LO, AROW, BPTR_HI, BPTR_LO, BROW)            \
    const __nv_bfloat16* segp[8];                                             \
    int dstoff[8];                                                            \
    _Pragma("unroll")                                                         \
    for (int i = 0; i < 8; i++) {                                             \
        int seg = i * 256 + tid;                                              \
        int part = seg >> 9;                                                  \
        int r = (seg >> 2) & 127;                                             \
        int s = seg & 3;                                                      \
        dstoff[i] = part * 8192 + (s >> 1) * 4096 + swz(r, s & 1);            \
        if (part < 2)                                                         \
            segp[i] = (part == 0 ? (APTR_HI) : (APTR_LO)) + (size_t)(AROW) * D + s * 8; \
        else                                                                  \
            segp[i] = (part == 2 ? (BPTR_HI) : (BPTR_LO)) + (size_t)(BROW) * D + s * 8; \
    }

#define ISSUE_STAGE(c)                                                        \
    do {                                                                      \
        uint32_t _sb = bufs_u + ((c) & (NSTAGE - 1)) * STAGE_B;               \
        int _k0 = (c) * KCH;                                                  \
        _Pragma("unroll")                                                     \
        for (int i = 0; i < 8; i++) cp16(_sb + dstoff[i], segp[i] + _k0);     \
    } while (0)

// ---------------- expert GEMM: Y[slot] = w * (X[tok] @ We[e]^T + be[e]) ------
__global__ __launch_bounds__(256, 1) void k_expert_gemm(const float* __restrict__ be)
{
    int e = blockIdx.z;
    int cnt = g_counts[e];
    int row0 = blockIdx.y * 128;
    if (row0 >= cnt) return;
    int n0 = blockIdx.x * 128;
    int off = g_off[e];

    extern __shared__ char smem[];
    int* sTok = (int*)smem;
    float* sW = (float*)(smem + 512);
    uint32_t bufs_u = smem_u32(smem + 1024);

    int tid = threadIdx.x, lane = tid & 31, warp = tid >> 5;
    int wm = warp >> 2, wn = warp & 3;
    const __nv_bfloat16* Whi = g_Wehi + (size_t)e * D * D;
    const __nv_bfloat16* Wlo = g_Welo + (size_t)e * D * D;

    if (tid < 128) {
        int rl = row0 + tid;
        bool v = rl < cnt;
        sTok[tid] = v ? g_perm[off + rl] : -1;
        sW[tid]   = v ? g_permw[off + rl] : 0.f;
    }
    __syncthreads();

    SETUP_LDSM_OFFS();

    // per-thread cp.async segment pointers (A: gathered token rows, clamped)
    const __nv_bfloat16* segp[8];
    int dstoff[8];
#pragma unroll
    for (int i = 0; i < 8; i++) {
        int seg = i * 256 + tid;
        int part = seg >> 9;
        int r = (seg >> 2) & 127;
        int s = seg & 3;
        dstoff[i] = part * 8192 + (s >> 1) * 4096 + swz(r, s & 1);
        if (part < 2) {
            int tk = sTok[r]; if (tk < 0) tk = 0;   // garbage row masked in epilogue
            segp[i] = (part == 0 ? g_Xhi : g_Xlo) + (size_t)tk * D + s * 8;
        } else {
            segp[i] = (part == 2 ? Whi : Wlo) + (size_t)(n0 + r) * D + s * 8;
        }
    }

    float acc[4][4][4];
#pragma unroll
    for (int mf = 0; mf < 4; mf++)
#pragma unroll
        for (int nf = 0; nf < 4; nf++)
#pragma unroll
            for (int q = 0; q < 4; q++) acc[mf][nf][q] = 0.f;

    // prologue: stages 0..NSTAGE-2 in flight
#pragma unroll
    for (int s = 0; s < NSTAGE - 1; s++) { ISSUE_STAGE(s); CP_COMMIT(); }

    for (int c = 0; c < NC; c++) {
        CP_WAIT2();
        __syncthreads();
        if (c + NSTAGE - 1 < NC) ISSUE_STAGE(c + NSTAGE - 1);
        CP_COMMIT();
        COMPUTE_STAGE(bufs_u + (c & (NSTAGE - 1)) * STAGE_B);
    }

    // epilogue
#pragma unroll
    for (int mf = 0; mf < 4; mf++) {
        int m0l = wm * 64 + mf * 16 + (lane >> 2);
#pragma unroll
        for (int nf = 0; nf < 4; nf++) {
            int n = wn * 32 + nf * 8 + (lane & 3) * 2;
            const float* bep = be + e * D + n0 + n;
            float b0 = bep[0], b1 = bep[1];
#pragma unroll
            for (int half = 0; half < 2; half++) {
                int m = m0l + half * 8;
                if (sTok[m] >= 0) {
                    float w = sW[m];
                    float2 o;
                    o.x = w * (acc[mf][nf][half * 2 + 0] + b0);
                    o.y = w * (acc[mf][nf][half * 2 + 1] + b1);
                    *(float2*)(g_Y + (size_t)(off + row0 + m) * D + n0 + n) = o;
                }
            }
        }
    }
}

// ---------------- output GEMM: out = C @ Wo^T + bo ---------------------------
__global__ __launch_bounds__(256, 1) void k_out_gemm(
    const float* __restrict__ bo, float* __restrict__ out)
{
    int m0 = blockIdx.y * 128;
    int n0 = blockIdx.x * 128;

    extern __shared__ char smem[];
    uint32_t bufs_u = smem_u32(smem + 1024);

    int tid = threadIdx.x, lane = tid & 31, warp = tid >> 5;
    int wm = warp >> 2, wn = warp & 3;

    SETUP_LDSM_OFFS();
    SETUP_SEGS(g_Chi, g_Clo, m0 + ((i * 256 + tid) >> 2 & 127),
               g_Wohi, g_Wolo, n0 + ((i * 256 + tid) >> 2 & 127));

    float acc[4][4][4];
#pragma unroll
    for (int mf = 0; mf < 4; mf++)
#pragma unroll
        for (int nf = 0; nf < 4; nf++)
#pragma unroll
            for (int q = 0; q < 4; q++) acc[mf][nf][q] = 0.f;

#pragma unroll
    for (int s = 0; s < NSTAGE - 1; s++) { ISSUE_STAGE(s); CP_COMMIT(); }

    for (int c = 0; c < NC; c++) {
        CP_WAIT2();
        __syncthreads();
        if (c + NSTAGE - 1 < NC) ISSUE_STAGE(c + NSTAGE - 1);
        CP_COMMIT();
        COMPUTE_STAGE(bufs_u + (c & (NSTAGE - 1)) * STAGE_B);
    }

#pragma unroll
    for (int mf = 0; mf < 4; mf++) {
        int m0l = wm * 64 + mf * 16 + (lane >> 2);
#pragma unroll
        for (int nf = 0; nf < 4; nf++) {
            int n = wn * 32 + nf * 8 + (lane & 3) * 2;
            const float* bop = bo + n0 + n;
            float b0 = bop[0], b1 = bop[1];
#pragma unroll
            for (int half = 0; half < 2; half++) {
                int m = m0l + half * 8;
                float2 o;
                o.x = acc[mf][nf][half * 2 + 0] + b0;
                o.y = acc[mf][nf][half * 2 + 1] + b1;
                *(float2*)(out + (size_t)(m0 + m) * D + n0 + n) = o;
            }
        }
    }
}

// ---------------- launch -----------------------------------------------------
extern "C" void kernel_launch(void* const* d_in, const int* in_sizes, int n_in,
                              void* d_out, int out_size)
{
    const float* X  = (const float*)d_in[0];
    const float* We = (const float*)d_in[1];
    const float* be = (const float*)d_in[2];
    const float* Wr = (const float*)d_in[3];
    const float* br = (const float*)d_in[4];
    const float* Wo = (const float*)d_in[5];
    const float* bo = (const float*)d_in[6];
    float* out = (float*)d_out;

    static int smem_set = 0;
    if (!smem_set) {
        cudaFuncSetAttribute(k_expert_gemm, cudaFuncAttributeMaxDynamicSharedMemorySize, SMEM_DYN);
        cudaFuncSetAttribute(k_out_gemm,    cudaFuncAttributeMaxDynamicSharedMemorySize, SMEM_DYN);
        smem_set = 1;
    }

    __nv_bfloat16 *xhi, *xlo, *wehi, *welo, *wohi, *wolo;
    cudaGetSymbolAddress((void**)&xhi,  g_Xhi);
    cudaGetSymbolAddress((void**)&xlo,  g_Xlo);
    cudaGetSymbolAddress((void**)&wehi, g_Wehi);
    cudaGetSymbolAddress((void**)&welo, g_Welo);
    cudaGetSymbolAddress((void**)&wohi, g_Wohi);
    cudaGetSymbolAddress((void**)&wolo, g_Wolo);

    k_init<<<1, 32>>>();
    k_convert<<<2048, 256>>>((const float4*)X,  (uint2*)xhi,  (uint2*)xlo,  T * D / 4);
    k_convert<<<2048, 256>>>((const float4*)We, (uint2*)wehi, (uint2*)welo, E * D * D / 4);
    k_convert<<<512,  256>>>((const float4*)Wo, (uint2*)wohi, (uint2*)wolo, D * D / 4);
    k_router<<<T / 8, 256>>>(X, Wr, br);
    k_scan<<<1, 1>>>();
    k_scatter<<<(2 * T) / 256, 256>>>();
    k_expert_gemm<<<dim3(D / 128, T / 128, E), 256, SMEM_DYN>>>(be);
    k_combine<<<T * D / 4 / 256, 256>>>();
    k_out_gemm<<<dim3(D / 128, T / 128), 256, SMEM_DYN>>>(bo, out);
}

// round 6
// speedup vs baseline: 3.2333x; 1.3407x over previous
#include <cuda_runtime.h>
#include <cuda_fp16.h>
#include <math.h>
#include <stdint.h>

#define T 16384          // B*S tokens
#define D 1024
#define E 8
#define ROWCAP (2*T + E*128)
#define KCH 32           // k per pipeline stage
#define NC (D/KCH)       // 32 chunks
#define NSTAGE 4
// per-stage layout (bytes): Ahi[2][4096] Bhi[2][4096] Blo[2][4096]
#define STAGE_B 24576
#define SMEM_DYN (1024 + NSTAGE*STAGE_B)

// ---------------- scratch ----------------------------------------------------
__device__ int   g_counts[E];
__device__ int   g_cursor[E];
__device__ int   g_off[E];
__device__ int   g_topk_e[2*T];
__device__ float g_topk_w[2*T];
__device__ int   g_perm[ROWCAP];
__device__ float g_permw[ROWCAP];
__device__ int   g_slot[2*T];
__device__ float g_Y[(size_t)ROWCAP * D];
// preconverted fp16 operands (A side: hi only; B side: hi+lo)
__device__ __half g_Xh[(size_t)T*D];
__device__ __half g_Weh[(size_t)E*D*D], g_Wel[(size_t)E*D*D];
__device__ __half g_Woh[(size_t)D*D],  g_Wol[(size_t)D*D];
__device__ __half g_Ch[(size_t)T*D];

// ---------------- helpers ----------------------------------------------------
__device__ __forceinline__ uint32_t smem_u32(const void* p) {
    uint32_t a;
    asm("{ .reg .u64 t; cvta.to.shared.u64 t, %1; cvt.u32.u64 %0, t; }" : "=r"(a) : "l"(p));
    return a;
}

__device__ __forceinline__ void ldsm4(uint32_t* r, uint32_t a) {
    asm volatile("ldmatrix.sync.aligned.m8n8.x4.shared.b16 {%0,%1,%2,%3}, [%4];"
        : "=r"(r[0]), "=r"(r[1]), "=r"(r[2]), "=r"(r[3]) : "r"(a));
}

__device__ __forceinline__ void mma_f16(float* d, const uint32_t* a, const uint32_t* b) {
    asm volatile("mma.sync.aligned.m16n8k16.row.col.f32.f16.f16.f32 "
        "{%0,%1,%2,%3},{%4,%5,%6,%7},{%8,%9},{%0,%1,%2,%3};"
        : "+f"(d[0]), "+f"(d[1]), "+f"(d[2]), "+f"(d[3])
        : "r"(a[0]), "r"(a[1]), "r"(a[2]), "r"(a[3]), "r"(b[0]), "r"(b[1]));
}

__device__ __forceinline__ void cp16(uint32_t dst, const void* src) {
    asm volatile("cp.async.cg.shared.global [%0], [%1], 16;" :: "r"(dst), "l"(src));
}
#define CP_COMMIT() asm volatile("cp.async.commit_group;" ::: "memory")
#define CP_WAIT2()  asm volatile("cp.async.wait_group 2;" ::: "memory")

// swizzled byte offset within a 4KB (128 rows x 32B) k16 sub-tile
__device__ __forceinline__ int swz(int r, int h) {
    return (((r << 1) | h) ^ ((r >> 2) & 1)) << 4;
}

// fp32x4 -> packed fp16x4 hi and lo
__device__ __forceinline__ void split4h(float4 v, uint2* ho, uint2* lo) {
    float a[4] = {v.x, v.y, v.z, v.w};
    unsigned short h[4], l[4];
#pragma unroll
    for (int i = 0; i < 4; i++) {
        __half hb = __float2half_rn(a[i]);
        h[i] = __half_as_ushort(hb);
        l[i] = __half_as_ushort(__float2half_rn(a[i] - __half2float(hb)));
    }
    *ho = make_uint2((uint32_t)h[0] | ((uint32_t)h[1] << 16),
                     (uint32_t)h[2] | ((uint32_t)h[3] << 16));
    *lo = make_uint2((uint32_t)l[0] | ((uint32_t)l[1] << 16),
                     (uint32_t)l[2] | ((uint32_t)l[3] << 16));
}

__device__ __forceinline__ uint2 pack4h(float4 v) {
    unsigned short h0 = __half_as_ushort(__float2half_rn(v.x));
    unsigned short h1 = __half_as_ushort(__float2half_rn(v.y));
    unsigned short h2 = __half_as_ushort(__float2half_rn(v.z));
    unsigned short h3 = __half_as_ushort(__float2half_rn(v.w));
    return make_uint2((uint32_t)h0 | ((uint32_t)h1 << 16),
                      (uint32_t)h2 | ((uint32_t)h3 << 16));
}

// ---------------- converts ---------------------------------------------------
__global__ __launch_bounds__(256) void k_convert_hl(
    const float4* __restrict__ in, uint2* __restrict__ hi,
    uint2* __restrict__ lo, int n4)
{
    for (int i = blockIdx.x * 256 + threadIdx.x; i < n4; i += gridDim.x * 256) {
        uint2 h, l;
        split4h(in[i], &h, &l);
        hi[i] = h; lo[i] = l;
    }
}

__global__ __launch_bounds__(256) void k_convert_h(
    const float4* __restrict__ in, uint2* __restrict__ hi, int n4)
{
    for (int i = blockIdx.x * 256 + threadIdx.x; i < n4; i += gridDim.x * 256)
        hi[i] = pack4h(in[i]);
}

// ---------------- init / router / scan / scatter -----------------------------
__global__ void k_init() {
    int i = threadIdx.x;
    if (i < E) { g_counts[i] = 0; g_cursor[i] = 0; }
}

__global__ __launch_bounds__(256) void k_router(
    const float* __restrict__ X, const float* __restrict__ Wr,
    const float* __restrict__ br)
{
    __shared__ float sWr[E * D];
    int tid = threadIdx.x;
    for (int i = tid; i < E * D; i += 256) sWr[i] = Wr[i];
    __syncthreads();

    int warp = tid >> 5, lane = tid & 31;
    int t = blockIdx.x * 8 + warp;
    const float* x = X + (size_t)t * D;

    float acc[E];
#pragma unroll
    for (int e = 0; e < E; e++) acc[e] = 0.f;
    for (int i = 0; i < D / 32; i++) {
        float xv = x[i * 32 + lane];
#pragma unroll
        for (int e = 0; e < E; e++) acc[e] += xv * sWr[e * D + i * 32 + lane];
    }
#pragma unroll
    for (int e = 0; e < E; e++) {
#pragma unroll
        for (int o = 16; o > 0; o >>= 1)
            acc[e] += __shfl_xor_sync(0xffffffffu, acc[e], o);
    }
    if (lane == 0) {
        float p[E], m = -1e30f;
#pragma unroll
        for (int e = 0; e < E; e++) { p[e] = acc[e] + br[e]; m = fmaxf(m, p[e]); }
        float s = 0.f;
#pragma unroll
        for (int e = 0; e < E; e++) { p[e] = expf(p[e] - m); s += p[e]; }
        float inv = 1.f / s;
#pragma unroll
        for (int e = 0; e < E; e++) p[e] *= inv;
        int e0 = 0;
#pragma unroll
        for (int e = 1; e < E; e++) if (p[e] > p[e0]) e0 = e;
        int e1 = (e0 == 0) ? 1 : 0;
#pragma unroll
        for (int e = 0; e < E; e++) if (e != e0 && p[e] > p[e1]) e1 = e;
        g_topk_e[2 * t + 0] = e0;  g_topk_w[2 * t + 0] = p[e0];
        g_topk_e[2 * t + 1] = e1;  g_topk_w[2 * t + 1] = p[e1];
        atomicAdd(&g_counts[e0], 1);
        atomicAdd(&g_counts[e1], 1);
    }
}

__global__ void k_scan() {
    if (threadIdx.x == 0) {
        int off = 0;
        for (int e = 0; e < E; e++) {
            g_off[e] = off;
            off += ((g_counts[e] + 127) / 128) * 128;
        }
    }
}

__global__ __launch_bounds__(256) void k_scatter() {
    int idx = blockIdx.x * 256 + threadIdx.x;
    if (idx >= 2 * T) return;
    int e = g_topk_e[idx];
    float w = g_topk_w[idx];
    int pos = atomicAdd(&g_cursor[e], 1);
    int slot = g_off[e] + pos;
    g_perm[slot]  = idx >> 1;
    g_permw[slot] = w;
    g_slot[idx]   = slot;
}

// ---------------- combine: C[t] = fp16(Y[s0]+Y[s1]) --------------------------
__global__ __launch_bounds__(256) void k_combine() {
    int idx = blockIdx.x * 256 + threadIdx.x;        // over T*D/4
    int t = idx >> 8;
    int c4 = idx & 255;
    int s0 = g_slot[2 * t + 0], s1 = g_slot[2 * t + 1];
    float4 a = ((const float4*)g_Y)[(size_t)s0 * 256 + c4];
    float4 b = ((const float4*)g_Y)[(size_t)s1 * 256 + c4];
    ((uint2*)g_Ch)[idx] = pack4h(make_float4(a.x + b.x, a.y + b.y, a.z + b.z, a.w + b.w));
}

// ===== shared compute: 2 k16 steps, 2-pass fp16 (A_hi*(B_hi+B_lo)) ===========
#define COMPUTE_STAGE(bufbase)                                                \
    do {                                                                      \
        _Pragma("unroll")                                                     \
        for (int ks = 0; ks < 2; ks++) {                                      \
            uint32_t ahB = (bufbase) + ks * 4096;                             \
            uint32_t bhB = (bufbase) + 8192 + ks * 4096;                      \
            uint32_t blB = (bufbase) + 16384 + ks * 4096;                     \
            uint32_t ahi[4][4], bhi[2][4], blo[2][4];                         \
            _Pragma("unroll")                                                 \
            for (int mf = 0; mf < 4; mf++) ldsm4(ahi[mf], ahB + aoff[mf]);    \
            _Pragma("unroll")                                                 \
            for (int p = 0; p < 2; p++) {                                     \
                ldsm4(bhi[p], bhB + boff[p]);                                 \
                ldsm4(blo[p], blB + boff[p]);                                 \
            }                                                                 \
            _Pragma("unroll")                                                 \
            for (int mf = 0; mf < 4; mf++)                                    \
                _Pragma("unroll")                                             \
                for (int nf = 0; nf < 4; nf++) {                              \
                    uint32_t* bh = &bhi[nf >> 1][(nf & 1) * 2];               \
                    uint32_t* bl = &blo[nf >> 1][(nf & 1) * 2];               \
                    mma_f16(acc[mf][nf], ahi[mf], bh);                        \
                    mma_f16(acc[mf][nf], ahi[mf], bl);                        \
                }                                                             \
        }                                                                     \
    } while (0)

#define SETUP_LDSM_OFFS()                                                     \
    int aoff[4], boff[2];                                                     \
    {                                                                         \
        int ar = lane & 15, ah = lane >> 4;                                   \
        _Pragma("unroll")                                                     \
        for (int mf = 0; mf < 4; mf++) aoff[mf] = swz(wm * 64 + mf * 16 + ar, ah); \
        int bj = lane >> 3;                                                   \
        int bn = (lane & 7) + ((bj >> 1) << 3);                               \
        int bh_ = bj & 1;                                                     \
        _Pragma("unroll")                                                     \
        for (int p = 0; p < 2; p++) boff[p] = swz(wn * 32 + p * 16 + bn, bh_);\
    }

// 6 x 16B segments per thread per stage: part = seg>>9 (0=Ahi,1=Bhi,2=Blo)
#define ISSUE_STAGE(c)                                                        \
    do {                                                                      \
        uint32_t _sb = bufs_u + ((c) & (NSTAGE - 1)) * STAGE_B;               \
        int _k0 = (c) * KCH;                                                  \
        _Pragma("unroll")                                                     \
        for (int i = 0; i < 6; i++) cp16(_sb + dstoff[i], segp[i] + _k0);     \
    } while (0)

// ---------------- expert GEMM: Y[slot] = w * (X[tok] @ We[e]^T + be[e]) ------
__global__ __launch_bounds__(256, 1) void k_expert_gemm(const float* __restrict__ be)
{
    int e = blockIdx.z;
    int cnt = g_counts[e];
    int row0 = blockIdx.y * 128;
    if (row0 >= cnt) return;
    int n0 = blockIdx.x * 128;
    int off = g_off[e];

    extern __shared__ char smem[];
    int* sTok = (int*)smem;
    float* sW = (float*)(smem + 512);
    uint32_t bufs_u = smem_u32(smem + 1024);

    int tid = threadIdx.x, lane = tid & 31, warp = tid >> 5;
    int wm = warp >> 2, wn = warp & 3;
    const __half* Whi = g_Weh + (size_t)e * D * D;
    const __half* Wlo = g_Wel + (size_t)e * D * D;

    if (tid < 128) {
        int rl = row0 + tid;
        bool v = rl < cnt;
        sTok[tid] = v ? g_perm[off + rl] : -1;
        sW[tid]   = v ? g_permw[off + rl] : 0.f;
    }
    __syncthreads();

    SETUP_LDSM_OFFS();

    const __half* segp[6];
    int dstoff[6];
#pragma unroll
    for (int i = 0; i < 6; i++) {
        int seg = i * 256 + tid;
        int part = seg >> 9;
        int r = (seg >> 2) & 127;
        int s = seg & 3;
        dstoff[i] = part * 8192 + (s >> 1) * 4096 + swz(r, s & 1);
        if (part == 0) {
            int tk = sTok[r]; if (tk < 0) tk = 0;   // garbage row masked in epilogue
            segp[i] = g_Xh + (size_t)tk * D + s * 8;
        } else {
            segp[i] = (part == 1 ? Whi : Wlo) + (size_t)(n0 + r) * D + s * 8;
        }
    }

    float acc[4][4][4];
#pragma unroll
    for (int mf = 0; mf < 4; mf++)
#pragma unroll
        for (int nf = 0; nf < 4; nf++)
#pragma unroll
            for (int q = 0; q < 4; q++) acc[mf][nf][q] = 0.f;

#pragma unroll
    for (int s = 0; s < NSTAGE - 1; s++) { ISSUE_STAGE(s); CP_COMMIT(); }

    for (int c = 0; c < NC; c++) {
        CP_WAIT2();
        __syncthreads();
        if (c + NSTAGE - 1 < NC) ISSUE_STAGE(c + NSTAGE - 1);
        CP_COMMIT();
        COMPUTE_STAGE(bufs_u + (c & (NSTAGE - 1)) * STAGE_B);
    }

    // epilogue
#pragma unroll
    for (int mf = 0; mf < 4; mf++) {
        int m0l = wm * 64 + mf * 16 + (lane >> 2);
#pragma unroll
        for (int nf = 0; nf < 4; nf++) {
            int n = wn * 32 + nf * 8 + (lane & 3) * 2;
            const float* bep = be + e * D + n0 + n;
            float b0 = bep[0], b1 = bep[1];
#pragma unroll
            for (int half = 0; half < 2; half++) {
                int m = m0l + half * 8;
                if (sTok[m] >= 0) {
                    float w = sW[m];
                    float2 o;
                    o.x = w * (acc[mf][nf][half * 2 + 0] + b0);
                    o.y = w * (acc[mf][nf][half * 2 + 1] + b1);
                    *(float2*)(g_Y + (size_t)(off + row0 + m) * D + n0 + n) = o;
                }
            }
        }
    }
}

// ---------------- output GEMM: out = C @ Wo^T + bo ---------------------------
__global__ __launch_bounds__(256, 1) void k_out_gemm(
    const float* __restrict__ bo, float* __restrict__ out)
{
    int m0 = blockIdx.y * 128;
    int n0 = blockIdx.x * 128;

    extern __shared__ char smem[];
    uint32_t bufs_u = smem_u32(smem + 1024);

    int tid = threadIdx.x, lane = tid & 31, warp = tid >> 5;
    int wm = warp >> 2, wn = warp & 3;

    SETUP_LDSM_OFFS();

    const __half* segp[6];
    int dstoff[6];
#pragma unroll
    for (int i = 0; i < 6; i++) {
        int seg = i * 256 + tid;
        int part = seg >> 9;
        int r = (seg >> 2) & 127;
        int s = seg & 3;
        dstoff[i] = part * 8192 + (s >> 1) * 4096 + swz(r, s & 1);
        if (part == 0)
            segp[i] = g_Ch + (size_t)(m0 + r) * D + s * 8;
        else
            segp[i] = (part == 1 ? g_Woh : g_Wol) + (size_t)(n0 + r) * D + s * 8;
    }

    float acc[4][4][4];
#pragma unroll
    for (int mf = 0; mf < 4; mf++)
#pragma unroll
        for (int nf = 0; nf < 4; nf++)
#pragma unroll
            for (int q = 0; q < 4; q++) acc[mf][nf][q] = 0.f;

#pragma unroll
    for (int s = 0; s < NSTAGE - 1; s++) { ISSUE_STAGE(s); CP_COMMIT(); }

    for (int c = 0; c < NC; c++) {
        CP_WAIT2();
        __syncthreads();
        if (c + NSTAGE - 1 < NC) ISSUE_STAGE(c + NSTAGE - 1);
        CP_COMMIT();
        COMPUTE_STAGE(bufs_u + (c & (NSTAGE - 1)) * STAGE_B);
    }

#pragma unroll
    for (int mf = 0; mf < 4; mf++) {
        int m0l = wm * 64 + mf * 16 + (lane >> 2);
#pragma unroll
        for (int nf = 0; nf < 4; nf++) {
            int n = wn * 32 + nf * 8 + (lane & 3) * 2;
            const float* bop = bo + n0 + n;
            float b0 = bop[0], b1 = bop[1];
#pragma unroll
            for (int half = 0; half < 2; half++) {
                int m = m0l + half * 8;
                float2 o;
                o.x = acc[mf][nf][half * 2 + 0] + b0;
                o.y = acc[mf][nf][half * 2 + 1] + b1;
                *(float2*)(out + (size_t)(m0 + m) * D + n0 + n) = o;
            }
        }
    }
}

// ---------------- launch -----------------------------------------------------
extern "C" void kernel_launch(void* const* d_in, const int* in_sizes, int n_in,
                              void* d_out, int out_size)
{
    const float* X  = (const float*)d_in[0];
    const float* We = (const float*)d_in[1];
    const float* be = (const float*)d_in[2];
    const float* Wr = (const float*)d_in[3];
    const float* br = (const float*)d_in[4];
    const float* Wo = (const float*)d_in[5];
    const float* bo = (const float*)d_in[6];
    float* out = (float*)d_out;

    static int smem_set = 0;
    if (!smem_set) {
        cudaFuncSetAttribute(k_expert_gemm, cudaFuncAttributeMaxDynamicSharedMemorySize, SMEM_DYN);
        cudaFuncSetAttribute(k_out_gemm,    cudaFuncAttributeMaxDynamicSharedMemorySize, SMEM_DYN);
        smem_set = 1;
    }

    __half *xh, *weh, *wel, *woh, *wol;
    cudaGetSymbolAddress((void**)&xh,  g_Xh);
    cudaGetSymbolAddress((void**)&weh, g_Weh);
    cudaGetSymbolAddress((void**)&wel, g_Wel);
    cudaGetSymbolAddress((void**)&woh, g_Woh);
    cudaGetSymbolAddress((void**)&wol, g_Wol);

    k_init<<<1, 32>>>();
    k_convert_h <<<1024, 256>>>((const float4*)X,  (uint2*)xh, T * D / 4);
    k_convert_hl<<<2048, 256>>>((const float4*)We, (uint2*)weh, (uint2*)wel, E * D * D / 4);
    k_convert_hl<<<512,  256>>>((const float4*)Wo, (uint2*)woh, (uint2*)wol, D * D / 4);
    k_router<<<T / 8, 256>>>(X, Wr, br);
    k_scan<<<1, 1>>>();
    k_scatter<<<(2 * T) / 256, 256>>>();
    k_expert_gemm<<<dim3(D / 128, T / 128, E), 256, SMEM_DYN>>>(be);
    k_combine<<<T * D / 4 / 256, 256>>>();
    k_out_gemm<<<dim3(D / 128, T / 128), 256, SMEM_DYN>>>(bo, out);
}

// round 7
// speedup vs baseline: 4.5756x; 1.4152x over previous
#include <cuda_runtime.h>
#include <cuda_fp16.h>
#include <math.h>
#include <stdint.h>

#define T 16384          // B*S tokens
#define D 1024
#define E 8
#define ROWCAP (2*T + E*128)
#define KCH 32           // k per pipeline stage
#define NC (D/KCH)       // 32 chunks
#define NSTAGE 4
// per-stage layout (bytes): Ahi[2][4096] Bhi[2][4096]
#define STAGE_B 16384
#define SMEM_DYN (1024 + NSTAGE*STAGE_B)

// ---------------- scratch ----------------------------------------------------
__device__ int   g_counts[E];
__device__ int   g_cursor[E];
__device__ int   g_off[E];
__device__ int   g_topk_e[2*T];
__device__ float g_topk_w[2*T];
__device__ int   g_perm[ROWCAP];
__device__ float g_permw[ROWCAP];
__device__ int   g_slot[2*T];
__device__ float g_Y[(size_t)ROWCAP * D];
// preconverted fp16 operands
__device__ __half g_Xh[(size_t)T*D];
__device__ __half g_Weh[(size_t)E*D*D];
__device__ __half g_Woh[(size_t)D*D];
__device__ __half g_Ch[(size_t)T*D];

// ---------------- helpers ----------------------------------------------------
__device__ __forceinline__ uint32_t smem_u32(const void* p) {
    uint32_t a;
    asm("{ .reg .u64 t; cvta.to.shared.u64 t, %1; cvt.u32.u64 %0, t; }" : "=r"(a) : "l"(p));
    return a;
}

__device__ __forceinline__ void ldsm4(uint32_t* r, uint32_t a) {
    asm volatile("ldmatrix.sync.aligned.m8n8.x4.shared.b16 {%0,%1,%2,%3}, [%4];"
        : "=r"(r[0]), "=r"(r[1]), "=r"(r[2]), "=r"(r[3]) : "r"(a));
}

__device__ __forceinline__ void mma_f16(float* d, const uint32_t* a, const uint32_t* b) {
    asm volatile("mma.sync.aligned.m16n8k16.row.col.f32.f16.f16.f32 "
        "{%0,%1,%2,%3},{%4,%5,%6,%7},{%8,%9},{%0,%1,%2,%3};"
        : "+f"(d[0]), "+f"(d[1]), "+f"(d[2]), "+f"(d[3])
        : "r"(a[0]), "r"(a[1]), "r"(a[2]), "r"(a[3]), "r"(b[0]), "r"(b[1]));
}

__device__ __forceinline__ void cp16(uint32_t dst, const void* src) {
    asm volatile("cp.async.cg.shared.global [%0], [%1], 16;" :: "r"(dst), "l"(src));
}
#define CP_COMMIT() asm volatile("cp.async.commit_group;" ::: "memory")
#define CP_WAIT2()  asm volatile("cp.async.wait_group 2;" ::: "memory")

// swizzled byte offset within a 4KB (128 rows x 32B) k16 sub-tile
__device__ __forceinline__ int swz(int r, int h) {
    return (((r << 1) | h) ^ ((r >> 2) & 1)) << 4;
}

__device__ __forceinline__ uint2 pack4h(float4 v) {
    unsigned short h0 = __half_as_ushort(__float2half_rn(v.x));
    unsigned short h1 = __half_as_ushort(__float2half_rn(v.y));
    unsigned short h2 = __half_as_ushort(__float2half_rn(v.z));
    unsigned short h3 = __half_as_ushort(__float2half_rn(v.w));
    return make_uint2((uint32_t)h0 | ((uint32_t)h1 << 16),
                      (uint32_t)h2 | ((uint32_t)h3 << 16));
}

// ---------------- convert: fp32 -> fp16 --------------------------------------
__global__ __launch_bounds__(256) void k_convert_h(
    const float4* __restrict__ in, uint2* __restrict__ hi, int n4)
{
    for (int i = blockIdx.x * 256 + threadIdx.x; i < n4; i += gridDim.x * 256)
        hi[i] = pack4h(in[i]);
}

// ---------------- init / router / scan / scatter -----------------------------
__global__ void k_init() {
    int i = threadIdx.x;
    if (i < E) { g_counts[i] = 0; g_cursor[i] = 0; }
}

__global__ __launch_bounds__(256) void k_router(
    const float* __restrict__ X, const float* __restrict__ Wr,
    const float* __restrict__ br)
{
    __shared__ float sWr[E * D];
    int tid = threadIdx.x;
    for (int i = tid; i < E * D; i += 256) sWr[i] = Wr[i];
    __syncthreads();

    int warp = tid >> 5, lane = tid & 31;
    int t = blockIdx.x * 8 + warp;
    const float* x = X + (size_t)t * D;

    float acc[E];
#pragma unroll
    for (int e = 0; e < E; e++) acc[e] = 0.f;
    for (int i = 0; i < D / 32; i++) {
        float xv = x[i * 32 + lane];
#pragma unroll
        for (int e = 0; e < E; e++) acc[e] += xv * sWr[e * D + i * 32 + lane];
    }
#pragma unroll
    for (int e = 0; e < E; e++) {
#pragma unroll
        for (int o = 16; o > 0; o >>= 1)
            acc[e] += __shfl_xor_sync(0xffffffffu, acc[e], o);
    }
    if (lane == 0) {
        float p[E], m = -1e30f;
#pragma unroll
        for (int e = 0; e < E; e++) { p[e] = acc[e] + br[e]; m = fmaxf(m, p[e]); }
        float s = 0.f;
#pragma unroll
        for (int e = 0; e < E; e++) { p[e] = expf(p[e] - m); s += p[e]; }
        float inv = 1.f / s;
#pragma unroll
        for (int e = 0; e < E; e++) p[e] *= inv;
        int e0 = 0;
#pragma unroll
        for (int e = 1; e < E; e++) if (p[e] > p[e0]) e0 = e;
        int e1 = (e0 == 0) ? 1 : 0;
#pragma unroll
        for (int e = 0; e < E; e++) if (e != e0 && p[e] > p[e1]) e1 = e;
        g_topk_e[2 * t + 0] = e0;  g_topk_w[2 * t + 0] = p[e0];
        g_topk_e[2 * t + 1] = e1;  g_topk_w[2 * t + 1] = p[e1];
        atomicAdd(&g_counts[e0], 1);
        atomicAdd(&g_counts[e1], 1);
    }
}

__global__ void k_scan() {
    if (threadIdx.x == 0) {
        int off = 0;
        for (int e = 0; e < E; e++) {
            g_off[e] = off;
            off += ((g_counts[e] + 127) / 128) * 128;
        }
    }
}

__global__ __launch_bounds__(256) void k_scatter() {
    int idx = blockIdx.x * 256 + threadIdx.x;
    if (idx >= 2 * T) return;
    int e = g_topk_e[idx];
    float w = g_topk_w[idx];
    int pos = atomicAdd(&g_cursor[e], 1);
    int slot = g_off[e] + pos;
    g_perm[slot]  = idx >> 1;
    g_permw[slot] = w;
    g_slot[idx]   = slot;
}

// ---------------- combine: C[t] = fp16(Y[s0]+Y[s1]) --------------------------
__global__ __launch_bounds__(256) void k_combine() {
    int idx = blockIdx.x * 256 + threadIdx.x;        // over T*D/4
    int t = idx >> 8;
    int c4 = idx & 255;
    int s0 = g_slot[2 * t + 0], s1 = g_slot[2 * t + 1];
    float4 a = ((const float4*)g_Y)[(size_t)s0 * 256 + c4];
    float4 b = ((const float4*)g_Y)[(size_t)s1 * 256 + c4];
    ((uint2*)g_Ch)[idx] = pack4h(make_float4(a.x + b.x, a.y + b.y, a.z + b.z, a.w + b.w));
}

// ===== shared compute: 2 k16 steps, single-pass fp16 =========================
#define COMPUTE_STAGE(bufbase)                                                \
    do {                                                                      \
        _Pragma("unroll")                                                     \
        for (int ks = 0; ks < 2; ks++) {                                      \
            uint32_t ahB = (bufbase) + ks * 4096;                             \
            uint32_t bhB = (bufbase) + 8192 + ks * 4096;                      \
            uint32_t ahi[4][4], bhi[2][4];                                    \
            _Pragma("unroll")                                                 \
            for (int mf = 0; mf < 4; mf++) ldsm4(ahi[mf], ahB + aoff[mf]);    \
            _Pragma("unroll")                                                 \
            for (int p = 0; p < 2; p++) ldsm4(bhi[p], bhB + boff[p]);         \
            _Pragma("unroll")                                                 \
            for (int mf = 0; mf < 4; mf++)                                    \
                _Pragma("unroll")                                             \
                for (int nf = 0; nf < 4; nf++)                                \
                    mma_f16(acc[mf][nf], ahi[mf], &bhi[nf >> 1][(nf & 1) * 2]); \
        }                                                                     \
    } while (0)

#define SETUP_LDSM_OFFS()                                                     \
    int aoff[4], boff[2];                                                     \
    {                                                                         \
        int ar = lane & 15, ah = lane >> 4;                                   \
        _Pragma("unroll")                                                     \
        for (int mf = 0; mf < 4; mf++) aoff[mf] = swz(wm * 64 + mf * 16 + ar, ah); \
        int bj = lane >> 3;                                                   \
        int bn = (lane & 7) + ((bj >> 1) << 3);                               \
        int bh_ = bj & 1;                                                     \
        _Pragma("unroll")                                                     \
        for (int p = 0; p < 2; p++) boff[p] = swz(wn * 32 + p * 16 + bn, bh_);\
    }

// 4 x 16B segments per thread per stage: part = seg>>9 (0=Ahi,1=Bhi)
#define ISSUE_STAGE(c)                                                        \
    do {                                                                      \
        uint32_t _sb = bufs_u + ((c) & (NSTAGE - 1)) * STAGE_B;               \
        int _k0 = (c) * KCH;                                                  \
        _Pragma("unroll")                                                     \
        for (int i = 0; i < 4; i++) cp16(_sb + dstoff[i], segp[i] + _k0);     \
    } while (0)

// ---------------- expert GEMM: Y[slot] = w * (X[tok] @ We[e]^T + be[e]) ------
__global__ __launch_bounds__(256, 1) void k_expert_gemm(const float* __restrict__ be)
{
    int e = blockIdx.z;
    int cnt = g_counts[e];
    int row0 = blockIdx.y * 128;
    if (row0 >= cnt) return;
    int n0 = blockIdx.x * 128;
    int off = g_off[e];

    extern __shared__ char smem[];
    int* sTok = (int*)smem;
    float* sW = (float*)(smem + 512);
    uint32_t bufs_u = smem_u32(smem + 1024);

    int tid = threadIdx.x, lane = tid & 31, warp = tid >> 5;
    int wm = warp >> 2, wn = warp & 3;
    const __half* Whi = g_Weh + (size_t)e * D * D;

    if (tid < 128) {
        int rl = row0 + tid;
        bool v = rl < cnt;
        sTok[tid] = v ? g_perm[off + rl] : -1;
        sW[tid]   = v ? g_permw[off + rl] : 0.f;
    }
    __syncthreads();

    SETUP_LDSM_OFFS();

    const __half* segp[4];
    int dstoff[4];
#pragma unroll
    for (int i = 0; i < 4; i++) {
        int seg = i * 256 + tid;
        int part = seg >> 9;
        int r = (seg >> 2) & 127;
        int s = seg & 3;
        dstoff[i] = part * 8192 + (s >> 1) * 4096 + swz(r, s & 1);
        if (part == 0) {
            int tk = sTok[r]; if (tk < 0) tk = 0;   // garbage row masked in epilogue
            segp[i] = g_Xh + (size_t)tk * D + s * 8;
        } else {
            segp[i] = Whi + (size_t)(n0 + r) * D + s * 8;
        }
    }

    float acc[4][4][4];
#pragma unroll
    for (int mf = 0; mf < 4; mf++)
#pragma unroll
        for (int nf = 0; nf < 4; nf++)
#pragma unroll
            for (int q = 0; q < 4; q++) acc[mf][nf][q] = 0.f;

#pragma unroll
    for (int s = 0; s < NSTAGE - 1; s++) { ISSUE_STAGE(s); CP_COMMIT(); }

    for (int c = 0; c < NC; c++) {
        CP_WAIT2();
        __syncthreads();
        if (c + NSTAGE - 1 < NC) ISSUE_STAGE(c + NSTAGE - 1);
        CP_COMMIT();
        COMPUTE_STAGE(bufs_u + (c & (NSTAGE - 1)) * STAGE_B);
    }

    // epilogue
#pragma unroll
    for (int mf = 0; mf < 4; mf++) {
        int m0l = wm * 64 + mf * 16 + (lane >> 2);
#pragma unroll
        for (int nf = 0; nf < 4; nf++) {
            int n = wn * 32 + nf * 8 + (lane & 3) * 2;
            const float* bep = be + e * D + n0 + n;
            float b0 = bep[0], b1 = bep[1];
#pragma unroll
            for (int half = 0; half < 2; half++) {
                int m = m0l + half * 8;
                if (sTok[m] >= 0) {
                    float w = sW[m];
                    float2 o;
                    o.x = w * (acc[mf][nf][half * 2 + 0] + b0);
                    o.y = w * (acc[mf][nf][half * 2 + 1] + b1);
                    *(float2*)(g_Y + (size_t)(off + row0 + m) * D + n0 + n) = o;
                }
            }
        }
    }
}

// ---------------- output GEMM: out = C @ Wo^T + bo ---------------------------
__global__ __launch_bounds__(256, 1) void k_out_gemm(
    const float* __restrict__ bo, float* __restrict__ out)
{
    int m0 = blockIdx.y * 128;
    int n0 = blockIdx.x * 128;

    extern __shared__ char smem[];
    uint32_t bufs_u = smem_u32(smem + 1024);

    int tid = threadIdx.x, lane = tid & 31, warp = tid >> 5;
    int wm = warp >> 2, wn = warp & 3;

    SETUP_LDSM_OFFS();

    const __half* segp[4];
    int dstoff[4];
#pragma unroll
    for (int i = 0; i < 4; i++) {
        int seg = i * 256 + tid;
        int part = seg >> 9;
        int r = (seg >> 2) & 127;
        int s = seg & 3;
        dstoff[i] = part * 8192 + (s >> 1) * 4096 + swz(r, s & 1);
        if (part == 0)
            segp[i] = g_Ch + (size_t)(m0 + r) * D + s * 8;
        else
            segp[i] = g_Woh + (size_t)(n0 + r) * D + s * 8;
    }

    float acc[4][4][4];
#pragma unroll
    for (int mf = 0; mf < 4; mf++)
#pragma unroll
        for (int nf = 0; nf < 4; nf++)
#pragma unroll
            for (int q = 0; q < 4; q++) acc[mf][nf][q] = 0.f;

#pragma unroll
    for (int s = 0; s < NSTAGE - 1; s++) { ISSUE_STAGE(s); CP_COMMIT(); }

    for (int c = 0; c < NC; c++) {
        CP_WAIT2();
        __syncthreads();
        if (c + NSTAGE - 1 < NC) ISSUE_STAGE(c + NSTAGE - 1);
        CP_COMMIT();
        COMPUTE_STAGE(bufs_u + (c & (NSTAGE - 1)) * STAGE_B);
    }

#pragma unroll
    for (int mf = 0; mf < 4; mf++) {
        int m0l = wm * 64 + mf * 16 + (lane >> 2);
#pragma unroll
        for (int nf = 0; nf < 4; nf++) {
            int n = wn * 32 + nf * 8 + (lane & 3) * 2;
            const float* bop = bo + n0 + n;
            float b0 = bop[0], b1 = bop[1];
#pragma unroll
            for (int half = 0; half < 2; half++) {
                int m = m0l + half * 8;
                float2 o;
                o.x = acc[mf][nf][half * 2 + 0] + b0;
                o.y = acc[mf][nf][half * 2 + 1] + b1;
                *(float2*)(out + (size_t)(m0 + m) * D + n0 + n) = o;
            }
        }
    }
}

// ---------------- launch -----------------------------------------------------
extern "C" void kernel_launch(void* const* d_in, const int* in_sizes, int n_in,
                              void* d_out, int out_size)
{
    const float* X  = (const float*)d_in[0];
    const float* We = (const float*)d_in[1];
    const float* be = (const float*)d_in[2];
    const float* Wr = (const float*)d_in[3];
    const float* br = (const float*)d_in[4];
    const float* Wo = (const float*)d_in[5];
    const float* bo = (const float*)d_in[6];
    float* out = (float*)d_out;

    static int smem_set = 0;
    if (!smem_set) {
        cudaFuncSetAttribute(k_expert_gemm, cudaFuncAttributeMaxDynamicSharedMemorySize, SMEM_DYN);
        cudaFuncSetAttribute(k_out_gemm,    cudaFuncAttributeMaxDynamicSharedMemorySize, SMEM_DYN);
        smem_set = 1;
    }

    __half *xh, *weh, *woh;
    cudaGetSymbolAddress((void**)&xh,  g_Xh);
    cudaGetSymbolAddress((void**)&weh, g_Weh);
    cudaGetSymbolAddress((void**)&woh, g_Woh);

    k_init<<<1, 32>>>();
    k_convert_h<<<1024, 256>>>((const float4*)X,  (uint2*)xh,  T * D / 4);
    k_convert_h<<<2048, 256>>>((const float4*)We, (uint2*)weh, E * D * D / 4);
    k_convert_h<<<512,  256>>>((const float4*)Wo, (uint2*)woh, D * D / 4);
    k_router<<<T / 8, 256>>>(X, Wr, br);
    k_scan<<<1, 1>>>();
    k_scatter<<<(2 * T) / 256, 256>>>();
    k_expert_gemm<<<dim3(D / 128, T / 128, E), 256, SMEM_DYN>>>(be);
    k_combine<<<T * D / 4 / 256, 256>>>();
    k_out_gemm<<<dim3(D / 128, T / 128), 256, SMEM_DYN>>>(bo, out);
}

// round 8
// speedup vs baseline: 5.9944x; 1.3101x over previous
#include <cuda_runtime.h>
#include <cuda_fp16.h>
#include <math.h>
#include <stdint.h>

#define T 16384          // B*S tokens
#define D 1024
#define E 8
#define ROWCAP (2*T + E*128)
#define KCH 32           // k per pipeline stage
#define NC (D/KCH)       // 32 chunks
#define NSTAGE 4
// per-stage layout (bytes): Ahi[2][4096] Bhi[2][4096]
#define STAGE_B 16384
#define SMEM_DYN (1024 + NSTAGE*STAGE_B)

// ---------------- scratch ----------------------------------------------------
__device__ int   g_counts[E];
__device__ int   g_cursor[E];
__device__ int   g_off[E];
__device__ int   g_topk_e[2*T];
__device__ float g_topk_w[2*T];
__device__ int   g_perm[ROWCAP];
__device__ float g_permw[ROWCAP];
__device__ int   g_slot[2*T];
__device__ __half g_Yh[(size_t)ROWCAP * D];   // fp16 expert outputs (weighted+biased)
// preconverted fp16 operands
__device__ __half g_Xh[(size_t)T*D];
__device__ __half g_Weh[(size_t)E*D*D];
__device__ __half g_Woh[(size_t)D*D];
__device__ __half g_Ch[(size_t)T*D];

// ---------------- helpers ----------------------------------------------------
__device__ __forceinline__ uint32_t smem_u32(const void* p) {
    uint32_t a;
    asm("{ .reg .u64 t; cvta.to.shared.u64 t, %1; cvt.u32.u64 %0, t; }" : "=r"(a) : "l"(p));
    return a;
}

__device__ __forceinline__ void ldsm4(uint32_t* r, uint32_t a) {
    asm volatile("ldmatrix.sync.aligned.m8n8.x4.shared.b16 {%0,%1,%2,%3}, [%4];"
        : "=r"(r[0]), "=r"(r[1]), "=r"(r[2]), "=r"(r[3]) : "r"(a));
}

__device__ __forceinline__ void mma_f16(float* d, const uint32_t* a, const uint32_t* b) {
    asm volatile("mma.sync.aligned.m16n8k16.row.col.f32.f16.f16.f32 "
        "{%0,%1,%2,%3},{%4,%5,%6,%7},{%8,%9},{%0,%1,%2,%3};"
        : "+f"(d[0]), "+f"(d[1]), "+f"(d[2]), "+f"(d[3])
        : "r"(a[0]), "r"(a[1]), "r"(a[2]), "r"(a[3]), "r"(b[0]), "r"(b[1]));
}

__device__ __forceinline__ void cp16(uint32_t dst, const void* src) {
    asm volatile("cp.async.cg.shared.global [%0], [%1], 16;" :: "r"(dst), "l"(src));
}
#define CP_COMMIT() asm volatile("cp.async.commit_group;" ::: "memory")
#define CP_WAIT2()  asm volatile("cp.async.wait_group 2;" ::: "memory")

// swizzled byte offset within a 4KB (128 rows x 32B) k16 sub-tile
__device__ __forceinline__ int swz(int r, int h) {
    return (((r << 1) | h) ^ ((r >> 2) & 1)) << 4;
}

__device__ __forceinline__ uint2 pack4h(float4 v) {
    unsigned short h0 = __half_as_ushort(__float2half_rn(v.x));
    unsigned short h1 = __half_as_ushort(__float2half_rn(v.y));
    unsigned short h2 = __half_as_ushort(__float2half_rn(v.z));
    unsigned short h3 = __half_as_ushort(__float2half_rn(v.w));
    return make_uint2((uint32_t)h0 | ((uint32_t)h1 << 16),
                      (uint32_t)h2 | ((uint32_t)h3 << 16));
}

// ---------------- convert: fp32 -> fp16 --------------------------------------
__global__ __launch_bounds__(256) void k_convert_h(
    const float4* __restrict__ in, uint2* __restrict__ hi, int n4)
{
    for (int i = blockIdx.x * 256 + threadIdx.x; i < n4; i += gridDim.x * 256)
        hi[i] = pack4h(in[i]);
}

// ---------------- init / router(+X convert) / scan / scatter -----------------
__global__ void k_init() {
    int i = threadIdx.x;
    if (i < E) { g_counts[i] = 0; g_cursor[i] = 0; }
}

__global__ __launch_bounds__(256) void k_router(
    const float* __restrict__ X, const float* __restrict__ Wr,
    const float* __restrict__ br)
{
    __shared__ float sWr[E * D];
    int tid = threadIdx.x;
    for (int i = tid; i < E * D; i += 256) sWr[i] = Wr[i];
    __syncthreads();

    int warp = tid >> 5, lane = tid & 31;
    int t = blockIdx.x * 8 + warp;
    const float* x = X + (size_t)t * D;

    // fused fp16 conversion of this token's row (wide loads, write g_Xh)
    {
        uint2* xo = (uint2*)(g_Xh + (size_t)t * D);
        const float4* xi = (const float4*)x;
#pragma unroll
        for (int i = 0; i < D / 4 / 32; i++)
            xo[i * 32 + lane] = pack4h(xi[i * 32 + lane]);
    }

    float acc[E];
#pragma unroll
    for (int e = 0; e < E; e++) acc[e] = 0.f;
    for (int i = 0; i < D / 32; i++) {
        float xv = x[i * 32 + lane];
#pragma unroll
        for (int e = 0; e < E; e++) acc[e] += xv * sWr[e * D + i * 32 + lane];
    }
#pragma unroll
    for (int e = 0; e < E; e++) {
#pragma unroll
        for (int o = 16; o > 0; o >>= 1)
            acc[e] += __shfl_xor_sync(0xffffffffu, acc[e], o);
    }
    if (lane == 0) {
        float p[E], m = -1e30f;
#pragma unroll
        for (int e = 0; e < E; e++) { p[e] = acc[e] + br[e]; m = fmaxf(m, p[e]); }
        float s = 0.f;
#pragma unroll
        for (int e = 0; e < E; e++) { p[e] = expf(p[e] - m); s += p[e]; }
        float inv = 1.f / s;
#pragma unroll
        for (int e = 0; e < E; e++) p[e] *= inv;
        int e0 = 0;
#pragma unroll
        for (int e = 1; e < E; e++) if (p[e] > p[e0]) e0 = e;
        int e1 = (e0 == 0) ? 1 : 0;
#pragma unroll
        for (int e = 0; e < E; e++) if (e != e0 && p[e] > p[e1]) e1 = e;
        g_topk_e[2 * t + 0] = e0;  g_topk_w[2 * t + 0] = p[e0];
        g_topk_e[2 * t + 1] = e1;  g_topk_w[2 * t + 1] = p[e1];
        atomicAdd(&g_counts[e0], 1);
        atomicAdd(&g_counts[e1], 1);
    }
}

__global__ void k_scan() {
    if (threadIdx.x == 0) {
        int off = 0;
        for (int e = 0; e < E; e++) {
            g_off[e] = off;
            off += ((g_counts[e] + 127) / 128) * 128;
        }
    }
}

__global__ __launch_bounds__(256) void k_scatter() {
    int idx = blockIdx.x * 256 + threadIdx.x;
    if (idx >= 2 * T) return;
    int e = g_topk_e[idx];
    float w = g_topk_w[idx];
    int pos = atomicAdd(&g_cursor[e], 1);
    int slot = g_off[e] + pos;
    g_perm[slot]  = idx >> 1;
    g_permw[slot] = w;
    g_slot[idx]   = slot;
}

// ---------------- combine: C[t] = Yh[s0] + Yh[s1] (fp16) ---------------------
__global__ __launch_bounds__(256) void k_combine() {
    int idx = blockIdx.x * 256 + threadIdx.x;        // over T*D/4
    int t = idx >> 8;
    int c4 = idx & 255;
    int s0 = g_slot[2 * t + 0], s1 = g_slot[2 * t + 1];
    uint2 a = ((const uint2*)g_Yh)[(size_t)s0 * 256 + c4];
    uint2 b = ((const uint2*)g_Yh)[(size_t)s1 * 256 + c4];
    __half2 r0 = __hadd2(*(__half2*)&a.x, *(__half2*)&b.x);
    __half2 r1 = __hadd2(*(__half2*)&a.y, *(__half2*)&b.y);
    uint2 o;
    o.x = *(uint32_t*)&r0; o.y = *(uint32_t*)&r1;
    ((uint2*)g_Ch)[idx] = o;
}

// ===== shared compute: 2 k16 steps, single-pass fp16 =========================
#define COMPUTE_STAGE(bufbase)                                                \
    do {                                                                      \
        _Pragma("unroll")                                                     \
        for (int ks = 0; ks < 2; ks++) {                                      \
            uint32_t ahB = (bufbase) + ks * 4096;                             \
            uint32_t bhB = (bufbase) + 8192 + ks * 4096;                      \
            uint32_t ahi[4][4], bhi[2][4];                                    \
            _Pragma("unroll")                                                 \
            for (int mf = 0; mf < 4; mf++) ldsm4(ahi[mf], ahB + aoff[mf]);    \
            _Pragma("unroll")                                                 \
            for (int p = 0; p < 2; p++) ldsm4(bhi[p], bhB + boff[p]);         \
            _Pragma("unroll")                                                 \
            for (int mf = 0; mf < 4; mf++)                                    \
                _Pragma("unroll")                                             \
                for (int nf = 0; nf < 4; nf++)                                \
                    mma_f16(acc[mf][nf], ahi[mf], &bhi[nf >> 1][(nf & 1) * 2]); \
        }                                                                     \
    } while (0)

#define SETUP_LDSM_OFFS()                                                     \
    int aoff[4], boff[2];                                                     \
    {                                                                         \
        int ar = lane & 15, ah = lane >> 4;                                   \
        _Pragma("unroll")                                                     \
        for (int mf = 0; mf < 4; mf++) aoff[mf] = swz(wm * 64 + mf * 16 + ar, ah); \
        int bj = lane >> 3;                                                   \
        int bn = (lane & 7) + ((bj >> 1) << 3);                               \
        int bh_ = bj & 1;                                                     \
        _Pragma("unroll")                                                     \
        for (int p = 0; p < 2; p++) boff[p] = swz(wn * 32 + p * 16 + bn, bh_);\
    }

// 4 x 16B segments per thread per stage: part = seg>>9 (0=Ahi,1=Bhi)
#define ISSUE_STAGE(c)                                                        \
    do {                                                                      \
        uint32_t _sb = bufs_u + ((c) & (NSTAGE - 1)) * STAGE_B;               \
        int _k0 = (c) * KCH;                                                  \
        _Pragma("unroll")                                                     \
        for (int i = 0; i < 4; i++) cp16(_sb + dstoff[i], segp[i] + _k0);     \
    } while (0)

// ---------------- expert GEMM: Yh[slot] = fp16(w*(X[tok]@We[e]^T+be[e])) -----
__global__ __launch_bounds__(256, 2) void k_expert_gemm(const float* __restrict__ be)
{
    int e = blockIdx.z;
    int cnt = g_counts[e];
    int row0 = blockIdx.y * 128;
    if (row0 >= cnt) return;
    int n0 = blockIdx.x * 128;
    int off = g_off[e];

    extern __shared__ char smem[];
    int* sTok = (int*)smem;
    float* sW = (float*)(smem + 512);
    uint32_t bufs_u = smem_u32(smem + 1024);

    int tid = threadIdx.x, lane = tid & 31, warp = tid >> 5;
    int wm = warp >> 2, wn = warp & 3;
    const __half* Whi = g_Weh + (size_t)e * D * D;

    if (tid < 128) {
        int rl = row0 + tid;
        bool v = rl < cnt;
        sTok[tid] = v ? g_perm[off + rl] : -1;
        sW[tid]   = v ? g_permw[off + rl] : 0.f;
    }
    __syncthreads();

    SETUP_LDSM_OFFS();

    const __half* segp[4];
    int dstoff[4];
#pragma unroll
    for (int i = 0; i < 4; i++) {
        int seg = i * 256 + tid;
        int part = seg >> 9;
        int r = (seg >> 2) & 127;
        int s = seg & 3;
        dstoff[i] = part * 8192 + (s >> 1) * 4096 + swz(r, s & 1);
        if (part == 0) {
            int tk = sTok[r]; if (tk < 0) tk = 0;   // garbage row masked in epilogue
            segp[i] = g_Xh + (size_t)tk * D + s * 8;
        } else {
            segp[i] = Whi + (size_t)(n0 + r) * D + s * 8;
        }
    }

    float acc[4][4][4];
#pragma unroll
    for (int mf = 0; mf < 4; mf++)
#pragma unroll
        for (int nf = 0; nf < 4; nf++)
#pragma unroll
            for (int q = 0; q < 4; q++) acc[mf][nf][q] = 0.f;

#pragma unroll
    for (int s = 0; s < NSTAGE - 1; s++) { ISSUE_STAGE(s); CP_COMMIT(); }

    for (int c = 0; c < NC; c++) {
        CP_WAIT2();
        __syncthreads();
        if (c + NSTAGE - 1 < NC) ISSUE_STAGE(c + NSTAGE - 1);
        CP_COMMIT();
        COMPUTE_STAGE(bufs_u + (c & (NSTAGE - 1)) * STAGE_B);
    }

    // epilogue (fp16 Y)
#pragma unroll
    for (int mf = 0; mf < 4; mf++) {
        int m0l = wm * 64 + mf * 16 + (lane >> 2);
#pragma unroll
        for (int nf = 0; nf < 4; nf++) {
            int n = wn * 32 + nf * 8 + (lane & 3) * 2;
            const float* bep = be + e * D + n0 + n;
            float b0 = bep[0], b1 = bep[1];
#pragma unroll
            for (int half = 0; half < 2; half++) {
                int m = m0l + half * 8;
                if (sTok[m] >= 0) {
                    float w = sW[m];
                    __half2 o = __halves2half2(
                        __float2half_rn(w * (acc[mf][nf][half * 2 + 0] + b0)),
                        __float2half_rn(w * (acc[mf][nf][half * 2 + 1] + b1)));
                    *(__half2*)(g_Yh + (size_t)(off + row0 + m) * D + n0 + n) = o;
                }
            }
        }
    }
}

// ---------------- output GEMM: out = C @ Wo^T + bo ---------------------------
__global__ __launch_bounds__(256, 2) void k_out_gemm(
    const float* __restrict__ bo, float* __restrict__ out)
{
    int m0 = blockIdx.y * 128;
    int n0 = blockIdx.x * 128;

    extern __shared__ char smem[];
    uint32_t bufs_u = smem_u32(smem + 1024);

    int tid = threadIdx.x, lane = tid & 31, warp = tid >> 5;
    int wm = warp >> 2, wn = warp & 3;

    SETUP_LDSM_OFFS();

    const __half* segp[4];
    int dstoff[4];
#pragma unroll
    for (int i = 0; i < 4; i++) {
        int seg = i * 256 + tid;
        int part = seg >> 9;
        int r = (seg >> 2) & 127;
        int s = seg & 3;
        dstoff[i] = part * 8192 + (s >> 1) * 4096 + swz(r, s & 1);
        if (part == 0)
            segp[i] = g_Ch + (size_t)(m0 + r) * D + s * 8;
        else
            segp[i] = g_Woh + (size_t)(n0 + r) * D + s * 8;
    }

    float acc[4][4][4];
#pragma unroll
    for (int mf = 0; mf < 4; mf++)
#pragma unroll
        for (int nf = 0; nf < 4; nf++)
#pragma unroll
            for (int q = 0; q < 4; q++) acc[mf][nf][q] = 0.f;

#pragma unroll
    for (int s = 0; s < NSTAGE - 1; s++) { ISSUE_STAGE(s); CP_COMMIT(); }

    for (int c = 0; c < NC; c++) {
        CP_WAIT2();
        __syncthreads();
        if (c + NSTAGE - 1 < NC) ISSUE_STAGE(c + NSTAGE - 1);
        CP_COMMIT();
        COMPUTE_STAGE(bufs_u + (c & (NSTAGE - 1)) * STAGE_B);
    }

#pragma unroll
    for (int mf = 0; mf < 4; mf++) {
        int m0l = wm * 64 + mf * 16 + (lane >> 2);
#pragma unroll
        for (int nf = 0; nf < 4; nf++) {
            int n = wn * 32 + nf * 8 + (lane & 3) * 2;
            const float* bop = bo + n0 + n;
            float b0 = bop[0], b1 = bop[1];
#pragma unroll
            for (int half = 0; half < 2; half++) {
                int m = m0l + half * 8;
                float2 o;
                o.x = acc[mf][nf][half * 2 + 0] + b0;
                o.y = acc[mf][nf][half * 2 + 1] + b1;
                *(float2*)(out + (size_t)(m0 + m) * D + n0 + n) = o;
            }
        }
    }
}

// ---------------- launch -----------------------------------------------------
extern "C" void kernel_launch(void* const* d_in, const int* in_sizes, int n_in,
                              void* d_out, int out_size)
{
    const float* X  = (const float*)d_in[0];
    const float* We = (const float*)d_in[1];
    const float* be = (const float*)d_in[2];
    const float* Wr = (const float*)d_in[3];
    const float* br = (const float*)d_in[4];
    const float* Wo = (const float*)d_in[5];
    const float* bo = (const float*)d_in[6];
    float* out = (float*)d_out;

    static int smem_set = 0;
    if (!smem_set) {
        cudaFuncSetAttribute(k_expert_gemm, cudaFuncAttributeMaxDynamicSharedMemorySize, SMEM_DYN);
        cudaFuncSetAttribute(k_out_gemm,    cudaFuncAttributeMaxDynamicSharedMemorySize, SMEM_DYN);
        smem_set = 1;
    }

    __half *weh, *woh;
    cudaGetSymbolAddress((void**)&weh, g_Weh);
    cudaGetSymbolAddress((void**)&woh, g_Woh);

    k_init<<<1, 32>>>();
    k_convert_h<<<2048, 256>>>((const float4*)We, (uint2*)weh, E * D * D / 4);
    k_convert_h<<<512,  256>>>((const float4*)Wo, (uint2*)woh, D * D / 4);
    k_router<<<T / 8, 256>>>(X, Wr, br);
    k_scan<<<1, 1>>>();
    k_scatter<<<(2 * T) / 256, 256>>>();
    k_expert_gemm<<<dim3(D / 128, T / 128, E), 256, SMEM_DYN>>>(be);
    k_combine<<<T * D / 4 / 256, 256>>>();
    k_out_gemm<<<dim3(D / 128, T / 128), 256, SMEM_DYN>>>(bo, out);
}